// round 2
// baseline (speedup 1.0000x reference)
#include <cuda_runtime.h>
#include <math.h>

#define D_MODEL   1024
#define NUM_HEADS 16
#define HEAD_DIM  64
#define BATCH     4
#define SEQ       2048
#define ROWS      (BATCH * SEQ)   // 8192

// Scratch (allocation-free rule: __device__ globals)
__device__ float g_Q[ROWS * D_MODEL];
__device__ float g_K[ROWS * D_MODEL];
__device__ float g_V[ROWS * D_MODEL];
__device__ float g_O[ROWS * D_MODEL];

// ---------------------------------------------------------------------------
// GEMM: out[8192,1024] = X[8192,1024] @ W[1024,1024] + bias, optional RoPE
// 128x128 block tile, BK=8, 256 threads, 8x8 micro-tile per thread.
// ---------------------------------------------------------------------------
template <int DO_ROPE>
__global__ void __launch_bounds__(256) gemm_bias_kernel(
    const float* __restrict__ X, const float* __restrict__ W,
    const float* __restrict__ bias, const int* __restrict__ pos,
    float* __restrict__ out)
{
    __shared__ float As[8][128];   // transposed: As[k][m]
    __shared__ float Bs[8][128];   // Bs[k][n]

    const int tid  = threadIdx.x;
    const int tx   = tid & 15;
    const int ty   = tid >> 4;
    const int row0 = blockIdx.y * 128;
    const int col0 = blockIdx.x * 128;

    const int a_row = tid >> 1;          // 0..127
    const int a_col = (tid & 1) * 4;     // 0 or 4
    const int b_row = tid >> 5;          // 0..7
    const int b_col = (tid & 31) * 4;    // 0..124

    float acc[8][8];
#pragma unroll
    for (int i = 0; i < 8; i++)
#pragma unroll
        for (int j = 0; j < 8; j++) acc[i][j] = 0.f;

    for (int k0 = 0; k0 < D_MODEL; k0 += 8) {
        float4 av = *(const float4*)&X[(row0 + a_row) * D_MODEL + k0 + a_col];
        float4 bv = *(const float4*)&W[(k0 + b_row) * D_MODEL + col0 + b_col];
        __syncthreads();
        As[a_col + 0][a_row] = av.x;
        As[a_col + 1][a_row] = av.y;
        As[a_col + 2][a_row] = av.z;
        As[a_col + 3][a_row] = av.w;
        *(float4*)&Bs[b_row][b_col] = bv;
        __syncthreads();
#pragma unroll
        for (int k = 0; k < 8; k++) {
            float a[8], b[8];
            *(float4*)&a[0] = *(const float4*)&As[k][ty * 8];
            *(float4*)&a[4] = *(const float4*)&As[k][ty * 8 + 4];
            *(float4*)&b[0] = *(const float4*)&Bs[k][tx * 8];
            *(float4*)&b[4] = *(const float4*)&Bs[k][tx * 8 + 4];
#pragma unroll
            for (int i = 0; i < 8; i++)
#pragma unroll
                for (int j = 0; j < 8; j++)
                    acc[i][j] = fmaf(a[i], b[j], acc[i][j]);
        }
    }

    float cb[8];
#pragma unroll
    for (int j = 0; j < 8; j++) cb[j] = bias[col0 + tx * 8 + j];

    if (DO_ROPE) {
        // interleaved RoPE: pair (even, odd) within each head_dim slice
        float invf[4];
#pragma unroll
        for (int j = 0; j < 8; j += 2) {
            int c  = col0 + tx * 8 + j;
            int ii = (c & (HEAD_DIM - 1)) >> 1;
            // THETA^(-(2i)/HEAD_DIM), log(10000) = 9.2103403719761836
            invf[j >> 1] = expf(-9.2103403719761836f * (float)(2 * ii) / (float)HEAD_DIM);
        }
#pragma unroll
        for (int i = 0; i < 8; i++) {
            int   r = row0 + ty * 8 + i;
            float p = (float)pos[r];
            float res[8];
#pragma unroll
            for (int j = 0; j < 8; j += 2) {
                float ang = p * invf[j >> 1];
                float sn, cs;
                sincosf(ang, &sn, &cs);
                float x1 = acc[i][j]     + cb[j];
                float x2 = acc[i][j + 1] + cb[j + 1];
                res[j]     = x1 * cs - x2 * sn;
                res[j + 1] = x1 * sn + x2 * cs;
            }
            float* dst = &out[r * D_MODEL + col0 + tx * 8];
            *(float4*)&dst[0] = make_float4(res[0], res[1], res[2], res[3]);
            *(float4*)&dst[4] = make_float4(res[4], res[5], res[6], res[7]);
        }
    } else {
#pragma unroll
        for (int i = 0; i < 8; i++) {
            int    r   = row0 + ty * 8 + i;
            float* dst = &out[r * D_MODEL + col0 + tx * 8];
            *(float4*)&dst[0] = make_float4(acc[i][0] + cb[0], acc[i][1] + cb[1],
                                            acc[i][2] + cb[2], acc[i][3] + cb[3]);
            *(float4*)&dst[4] = make_float4(acc[i][4] + cb[4], acc[i][5] + cb[5],
                                            acc[i][6] + cb[6], acc[i][7] + cb[7]);
        }
    }
}

// ---------------------------------------------------------------------------
// Flash attention fp32, causal. One CTA per (b, h, 64-row q-tile).
// 256 threads. k-tiles of 64 in smem, online softmax, PV in registers.
// ---------------------------------------------------------------------------
#define SCS 68   // padded row stride for Qs/Kt/Sc
static constexpr int ATTN_SMEM_FLOATS = 64 * SCS * 3 + 64 * 64;
static constexpr int ATTN_SMEM_BYTES  = ATTN_SMEM_FLOATS * 4;   // 68608 B

__global__ void __launch_bounds__(256) attn_kernel()
{
    extern __shared__ float sm[];
    float* Qs = sm;                 // [64][SCS]
    float* Kt = Qs + 64 * SCS;      // [64][SCS]
    float* Sc = Kt + 64 * SCS;      // [64][SCS]
    float* Vt = Sc + 64 * SCS;      // [64][64]

    const int tid   = threadIdx.x;
    const int qtile = blockIdx.x;
    const int h     = blockIdx.y;
    const int b     = blockIdx.z;
    const int qrow0 = b * SEQ + qtile * 64;
    const int cb    = h * HEAD_DIM;

    // load Q tile (64x64) into padded smem
#pragma unroll
    for (int it = 0; it < 4; it++) {
        int e = it * 256 + tid;            // float4 index 0..1023
        int r = e >> 4, c = (e & 15) * 4;
        *(float4*)&Qs[r * SCS + c] =
            *(const float4*)&g_Q[(qrow0 + r) * D_MODEL + cb + c];
    }

    const int tx   = tid & 15, ty = tid >> 4;   // score micro-tile mapping
    const int ro   = tid >> 2;                  // output row 0..63
    const int dseg = (tid & 3) * 16;            // output dim segment

    float o[16];
#pragma unroll
    for (int i = 0; i < 16; i++) o[i] = 0.f;
    float m_r = -1e30f, l_r = 0.f;              // per-row state (group of 4 threads)

    for (int jt = 0; jt <= qtile; jt++) {
        __syncthreads();   // prev PV / scores done before overwriting tiles
        const int krow0 = b * SEQ + jt * 64;
#pragma unroll
        for (int it = 0; it < 4; it++) {
            int e = it * 256 + tid;
            int r = e >> 4, c = (e & 15) * 4;
            *(float4*)&Kt[r * SCS + c] =
                *(const float4*)&g_K[(krow0 + r) * D_MODEL + cb + c];
            *(float4*)&Vt[r * 64 + c] =
                *(const float4*)&g_V[(krow0 + r) * D_MODEL + cb + c];
        }
        __syncthreads();

        // scores: S = Q K^T * 0.125, rows ty*4+i, cols tx*4+j
        float s[4][4];
#pragma unroll
        for (int i = 0; i < 4; i++)
#pragma unroll
            for (int j = 0; j < 4; j++) s[i][j] = 0.f;
#pragma unroll
        for (int d = 0; d < 64; d += 4) {
            float4 qv[4], kv[4];
#pragma unroll
            for (int i = 0; i < 4; i++)
                qv[i] = *(const float4*)&Qs[(ty * 4 + i) * SCS + d];
#pragma unroll
            for (int j = 0; j < 4; j++)
                kv[j] = *(const float4*)&Kt[(tx * 4 + j) * SCS + d];
#pragma unroll
            for (int i = 0; i < 4; i++)
#pragma unroll
                for (int j = 0; j < 4; j++) {
                    s[i][j] = fmaf(qv[i].x, kv[j].x, s[i][j]);
                    s[i][j] = fmaf(qv[i].y, kv[j].y, s[i][j]);
                    s[i][j] = fmaf(qv[i].z, kv[j].z, s[i][j]);
                    s[i][j] = fmaf(qv[i].w, kv[j].w, s[i][j]);
                }
        }
        const bool diag = (jt == qtile);
#pragma unroll
        for (int i = 0; i < 4; i++) {
            int    qi = ty * 4 + i;
            float4 wv = make_float4(s[i][0] * 0.125f, s[i][1] * 0.125f,
                                    s[i][2] * 0.125f, s[i][3] * 0.125f);
            if (diag) {
                int kq = tx * 4;
                if (kq + 0 > qi) wv.x = -1e30f;
                if (kq + 1 > qi) wv.y = -1e30f;
                if (kq + 2 > qi) wv.z = -1e30f;
                if (kq + 3 > qi) wv.w = -1e30f;
            }
            *(float4*)&Sc[qi * SCS + tx * 4] = wv;
        }
        __syncthreads();

        // online softmax: 4 threads per row (same grouping as PV mapping)
        {
            float mt = -1e30f;
#pragma unroll
            for (int k = 0; k < 16; k++)
                mt = fmaxf(mt, Sc[ro * SCS + dseg + k]);
            mt = fmaxf(mt, __shfl_xor_sync(0xffffffffu, mt, 1));
            mt = fmaxf(mt, __shfl_xor_sync(0xffffffffu, mt, 2));
            float mn  = fmaxf(m_r, mt);
            float f   = __expf(m_r - mn);
            float sum = 0.f;
#pragma unroll
            for (int k = 0; k < 16; k++) {
                float pv = __expf(Sc[ro * SCS + dseg + k] - mn);
                Sc[ro * SCS + dseg + k] = pv;
                sum += pv;
            }
            sum += __shfl_xor_sync(0xffffffffu, sum, 1);
            sum += __shfl_xor_sync(0xffffffffu, sum, 2);
            l_r = l_r * f + sum;
            m_r = mn;
#pragma unroll
            for (int i = 0; i < 16; i++) o[i] *= f;
        }
        __syncthreads();

        // O += P @ V
#pragma unroll 2
        for (int k = 0; k < 64; k++) {
            float  pv = Sc[ro * SCS + k];
            float4 v0 = *(const float4*)&Vt[k * 64 + dseg + 0];
            float4 v1 = *(const float4*)&Vt[k * 64 + dseg + 4];
            float4 v2 = *(const float4*)&Vt[k * 64 + dseg + 8];
            float4 v3 = *(const float4*)&Vt[k * 64 + dseg + 12];
            o[0]  = fmaf(pv, v0.x, o[0]);   o[1]  = fmaf(pv, v0.y, o[1]);
            o[2]  = fmaf(pv, v0.z, o[2]);   o[3]  = fmaf(pv, v0.w, o[3]);
            o[4]  = fmaf(pv, v1.x, o[4]);   o[5]  = fmaf(pv, v1.y, o[5]);
            o[6]  = fmaf(pv, v1.z, o[6]);   o[7]  = fmaf(pv, v1.w, o[7]);
            o[8]  = fmaf(pv, v2.x, o[8]);   o[9]  = fmaf(pv, v2.y, o[9]);
            o[10] = fmaf(pv, v2.z, o[10]);  o[11] = fmaf(pv, v2.w, o[11]);
            o[12] = fmaf(pv, v3.x, o[12]);  o[13] = fmaf(pv, v3.y, o[13]);
            o[14] = fmaf(pv, v3.z, o[14]);  o[15] = fmaf(pv, v3.w, o[15]);
        }
    }

    const float inv = 1.f / l_r;
#pragma unroll
    for (int i = 0; i < 16; i++) o[i] *= inv;
    float* dst = &g_O[(qrow0 + ro) * D_MODEL + cb + dseg];
    *(float4*)&dst[0]  = make_float4(o[0],  o[1],  o[2],  o[3]);
    *(float4*)&dst[4]  = make_float4(o[4],  o[5],  o[6],  o[7]);
    *(float4*)&dst[8]  = make_float4(o[8],  o[9],  o[10], o[11]);
    *(float4*)&dst[12] = make_float4(o[12], o[13], o[14], o[15]);
}

// ---------------------------------------------------------------------------
extern "C" void kernel_launch(void* const* d_in, const int* in_sizes, int n_in,
                              void* d_out, int out_size)
{
    (void)in_sizes; (void)n_in; (void)out_size;
    const float* query = (const float*)d_in[0];
    const float* key_  = (const float*)d_in[1];
    const float* value = (const float*)d_in[2];
    const int*   pos   = (const int*)d_in[3];
    const float* w_q   = (const float*)d_in[4];
    const float* b_q   = (const float*)d_in[5];
    const float* w_k   = (const float*)d_in[6];
    const float* b_k   = (const float*)d_in[7];
    const float* w_v   = (const float*)d_in[8];
    const float* b_v   = (const float*)d_in[9];
    const float* w_o   = (const float*)d_in[10];
    const float* b_o   = (const float*)d_in[11];
    float* out = (float*)d_out;

    float *pQ, *pK, *pV, *pO;
    cudaGetSymbolAddress((void**)&pQ, g_Q);
    cudaGetSymbolAddress((void**)&pK, g_K);
    cudaGetSymbolAddress((void**)&pV, g_V);
    cudaGetSymbolAddress((void**)&pO, g_O);

    cudaFuncSetAttribute(attn_kernel,
                         cudaFuncAttributeMaxDynamicSharedMemorySize,
                         ATTN_SMEM_BYTES);

    dim3 ggrid(D_MODEL / 128, ROWS / 128);   // (8, 64)
    gemm_bias_kernel<1><<<ggrid, 256>>>(query, w_q, b_q, pos, pQ);
    gemm_bias_kernel<1><<<ggrid, 256>>>(key_,  w_k, b_k, pos, pK);
    gemm_bias_kernel<0><<<ggrid, 256>>>(value, w_v, b_v, nullptr, pV);
    attn_kernel<<<dim3(SEQ / 64, NUM_HEADS, BATCH), 256, ATTN_SMEM_BYTES>>>();
    gemm_bias_kernel<0><<<ggrid, 256>>>(pO, w_o, b_o, nullptr, out);
}

// round 7
// speedup vs baseline: 1.2912x; 1.2912x over previous
#include <cuda_runtime.h>
#include <math.h>
#include <cstdint>

#define D_MODEL   1024
#define NUM_HEADS 16
#define HEAD_DIM  64
#define BATCH     4
#define SEQ       2048
#define ROWS      (BATCH * SEQ)   // 8192

// Scratch (allocation-free rule: __device__ globals)
__device__ float g_Q[ROWS * D_MODEL];
__device__ float g_K[ROWS * D_MODEL];
__device__ float g_V[ROWS * D_MODEL];
__device__ float g_O[ROWS * D_MODEL];
__device__ float g_WT[4 * D_MODEL * D_MODEL];   // transposed weights

// ===========================================================================
// Helpers (arch-agnostic PTX only: cp.async + mma.sync tf32)
// ===========================================================================
__device__ __forceinline__ uint32_t smem_u32(const void* p) {
    uint32_t a;
    asm("{ .reg .u64 t; cvta.to.shared.u64 t, %1; cvt.u32.u64 %0, t; }"
        : "=r"(a) : "l"(p));
    return a;
}
__device__ __forceinline__ void cp_async16(uint32_t dst, const void* src) {
    asm volatile("cp.async.cg.shared.global [%0], [%1], 16;"
                 :: "r"(dst), "l"(src) : "memory");
}
__device__ __forceinline__ void cp_commit() {
    asm volatile("cp.async.commit_group;" ::: "memory");
}
template <int N>
__device__ __forceinline__ void cp_wait() {
    asm volatile("cp.async.wait_group %0;" :: "n"(N) : "memory");
}
__device__ __forceinline__ uint32_t f2tf(float x) {
    uint32_t r;
    asm("cvt.rna.tf32.f32 %0, %1;" : "=r"(r) : "f"(x));
    return r;
}
__device__ __forceinline__ void mma_tf32(float* c, const uint32_t* a,
                                         const uint32_t* b) {
    asm volatile(
        "mma.sync.aligned.m16n8k8.row.col.f32.tf32.tf32.f32 "
        "{%0,%1,%2,%3}, {%4,%5,%6,%7}, {%8,%9}, {%0,%1,%2,%3};"
        : "+f"(c[0]), "+f"(c[1]), "+f"(c[2]), "+f"(c[3])
        : "r"(a[0]), "r"(a[1]), "r"(a[2]), "r"(a[3]), "r"(b[0]), "r"(b[1]));
}

// ===========================================================================
// Weight transpose: WT[n][k] = W[k][n]  (1024x1024)
// ===========================================================================
__global__ void __launch_bounds__(256) transpose_kernel(
    const float* __restrict__ in, float* __restrict__ out)
{
    __shared__ float t[32][33];
    const int bx = blockIdx.x * 32, by = blockIdx.y * 32;
#pragma unroll
    for (int i = threadIdx.y; i < 32; i += 8)
        t[i][threadIdx.x] = in[(size_t)(by + i) * D_MODEL + bx + threadIdx.x];
    __syncthreads();
#pragma unroll
    for (int i = threadIdx.y; i < 32; i += 8)
        out[(size_t)(bx + i) * D_MODEL + by + threadIdx.x] = t[threadIdx.x][i];
}

// ===========================================================================
// TF32 mma.sync GEMM: out[8192,1024] = X @ W + bias (W passed TRANSPOSED),
// optional fused interleaved RoPE.
// CTA tile 128x128, BK=16, 256 threads (8 warps, 2x4), warp tile 64x32.
// Double-buffered cp.async staging, stride-20 padded smem (conflict-free
// fragment loads for the (group, tig) lane mapping).
// ===========================================================================
#define BK      16
#define SSTR    20                    // padded row stride (floats)
#define NKIT    (D_MODEL / BK)        // 64

template <int DO_ROPE>
__global__ void __launch_bounds__(256, 1) gemm_tc(
    const float* __restrict__ X, const float* __restrict__ WT,
    const float* __restrict__ bias, const int* __restrict__ pos,
    float* __restrict__ out)
{
    __shared__ float As[2][128 * SSTR];
    __shared__ float Bs[2][128 * SSTR];

    const int tid  = threadIdx.x;
    const int wid  = tid >> 5, lid = tid & 31;
    const int g    = lid >> 2;        // groupID   0..7
    const int t    = lid & 3;         // tig       0..3
    const int row0 = blockIdx.y * 128;
    const int col0 = blockIdx.x * 128;
    const int warpM = (wid >> 2) * 64;    // 0 or 64
    const int warpN = (wid & 3) * 32;     // 0..96

    // staging indices: 512 float4 per tile, 2 per thread
    const int r_a  = tid >> 1;                 // unused pattern kept simple below

    float c[4][4][4];
#pragma unroll
    for (int i = 0; i < 4; i++)
#pragma unroll
        for (int j = 0; j < 4; j++)
#pragma unroll
            for (int q = 0; q < 4; q++) c[i][j][q] = 0.f;

    auto stage = [&](int buf, int it) {
        const float* aSrc = X  + (size_t)row0 * D_MODEL + it * BK;
        const float* bSrc = WT + (size_t)col0 * D_MODEL + it * BK;
#pragma unroll
        for (int rep = 0; rep < 2; rep++) {
            int idx = rep * 256 + tid;          // 0..511
            int r = idx >> 2, c4 = (idx & 3) * 4;
            cp_async16(smem_u32(&As[buf][r * SSTR + c4]),
                       aSrc + (size_t)r * D_MODEL + c4);
            cp_async16(smem_u32(&Bs[buf][r * SSTR + c4]),
                       bSrc + (size_t)r * D_MODEL + c4);
        }
        cp_commit();
    };

    stage(0, 0);

#pragma unroll 1
    for (int it = 0; it < NKIT; it++) {
        const int buf = it & 1;
        if (it + 1 < NKIT) {
            stage(buf ^ 1, it + 1);
            cp_wait<1>();
        } else {
            cp_wait<0>();
        }
        __syncthreads();

#pragma unroll
        for (int ks = 0; ks < 2; ks++) {
            const int k0 = ks * 8;
            uint32_t af[4][4], bf[4][2];
#pragma unroll
            for (int i = 0; i < 4; i++) {
                const float* base = &As[buf][(warpM + i * 16 + g) * SSTR + k0];
                af[i][0] = f2tf(base[t]);
                af[i][1] = f2tf(base[8 * SSTR + t]);
                af[i][2] = f2tf(base[t + 4]);
                af[i][3] = f2tf(base[8 * SSTR + t + 4]);
            }
#pragma unroll
            for (int j = 0; j < 4; j++) {
                const float* base = &Bs[buf][(warpN + j * 8 + g) * SSTR + k0];
                bf[j][0] = f2tf(base[t]);
                bf[j][1] = f2tf(base[t + 4]);
            }
#pragma unroll
            for (int i = 0; i < 4; i++)
#pragma unroll
                for (int j = 0; j < 4; j++)
                    mma_tf32(c[i][j], af[i], bf[j]);
        }
        __syncthreads();
    }

    // ---- epilogue: bias (+RoPE) in registers, float2 stores ----
    float invf[4];
    if (DO_ROPE) {
#pragma unroll
        for (int j = 0; j < 4; j++) {
            int cg = col0 + warpN + j * 8 + 2 * t;
            int ii = (cg & (HEAD_DIM - 1)) >> 1;
            invf[j] = expf(-0.287823137f * (float)ii);   // ln(1e4)/32
        }
    }
#pragma unroll
    for (int i = 0; i < 4; i++) {
        const int r0 = row0 + warpM + i * 16 + g;
        const int r1 = r0 + 8;
        float p0 = 0.f, p1 = 0.f;
        if (DO_ROPE) { p0 = (float)pos[r0]; p1 = (float)pos[r1]; }
#pragma unroll
        for (int j = 0; j < 4; j++) {
            const int cg = col0 + warpN + j * 8 + 2 * t;
            const float b0 = bias[cg], b1 = bias[cg + 1];
            float x0 = c[i][j][0] + b0, x1 = c[i][j][1] + b1;
            float y0 = c[i][j][2] + b0, y1 = c[i][j][3] + b1;
            if (DO_ROPE) {
                float sn, cs;
                sincosf(p0 * invf[j], &sn, &cs);
                float t0 = x0 * cs - x1 * sn, t1 = x0 * sn + x1 * cs;
                x0 = t0; x1 = t1;
                sincosf(p1 * invf[j], &sn, &cs);
                t0 = y0 * cs - y1 * sn; t1 = y0 * sn + y1 * cs;
                y0 = t0; y1 = t1;
            }
            *(float2*)&out[(size_t)r0 * D_MODEL + cg] = make_float2(x0, x1);
            *(float2*)&out[(size_t)r1 * D_MODEL + cg] = make_float2(y0, y1);
        }
    }
}

// ---------------------------------------------------------------------------
// Flash attention fp32, causal (unchanged — passed R1).
// ---------------------------------------------------------------------------
#define SCS 68
static constexpr int ATTN_SMEM_FLOATS = 64 * SCS * 3 + 64 * 64;
static constexpr int ATTN_SMEM_BYTES  = ATTN_SMEM_FLOATS * 4;

__global__ void __launch_bounds__(256) attn_kernel()
{
    extern __shared__ float smf[];
    float* Qs = smf;
    float* Kt = Qs + 64 * SCS;
    float* Sc = Kt + 64 * SCS;
    float* Vt = Sc + 64 * SCS;

    const int tid   = threadIdx.x;
    const int qtile = blockIdx.x;
    const int h     = blockIdx.y;
    const int b     = blockIdx.z;
    const int qrow0 = b * SEQ + qtile * 64;
    const int cb    = h * HEAD_DIM;

#pragma unroll
    for (int it = 0; it < 4; it++) {
        int e = it * 256 + tid;
        int r = e >> 4, c = (e & 15) * 4;
        *(float4*)&Qs[r * SCS + c] =
            *(const float4*)&g_Q[(qrow0 + r) * D_MODEL + cb + c];
    }

    const int tx   = tid & 15, ty = tid >> 4;
    const int ro   = tid >> 2;
    const int dseg = (tid & 3) * 16;

    float o[16];
#pragma unroll
    for (int i = 0; i < 16; i++) o[i] = 0.f;
    float m_r = -1e30f, l_r = 0.f;

    for (int jt = 0; jt <= qtile; jt++) {
        __syncthreads();
        const int krow0 = b * SEQ + jt * 64;
#pragma unroll
        for (int it = 0; it < 4; it++) {
            int e = it * 256 + tid;
            int r = e >> 4, c = (e & 15) * 4;
            *(float4*)&Kt[r * SCS + c] =
                *(const float4*)&g_K[(krow0 + r) * D_MODEL + cb + c];
            *(float4*)&Vt[r * 64 + c] =
                *(const float4*)&g_V[(krow0 + r) * D_MODEL + cb + c];
        }
        __syncthreads();

        float s[4][4];
#pragma unroll
        for (int i = 0; i < 4; i++)
#pragma unroll
            for (int j = 0; j < 4; j++) s[i][j] = 0.f;
#pragma unroll
        for (int d = 0; d < 64; d += 4) {
            float4 qv[4], kv[4];
#pragma unroll
            for (int i = 0; i < 4; i++)
                qv[i] = *(const float4*)&Qs[(ty * 4 + i) * SCS + d];
#pragma unroll
            for (int j = 0; j < 4; j++)
                kv[j] = *(const float4*)&Kt[(tx * 4 + j) * SCS + d];
#pragma unroll
            for (int i = 0; i < 4; i++)
#pragma unroll
                for (int j = 0; j < 4; j++) {
                    s[i][j] = fmaf(qv[i].x, kv[j].x, s[i][j]);
                    s[i][j] = fmaf(qv[i].y, kv[j].y, s[i][j]);
                    s[i][j] = fmaf(qv[i].z, kv[j].z, s[i][j]);
                    s[i][j] = fmaf(qv[i].w, kv[j].w, s[i][j]);
                }
        }
        const bool diag = (jt == qtile);
#pragma unroll
        for (int i = 0; i < 4; i++) {
            int    qi = ty * 4 + i;
            float4 wv = make_float4(s[i][0] * 0.125f, s[i][1] * 0.125f,
                                    s[i][2] * 0.125f, s[i][3] * 0.125f);
            if (diag) {
                int kq = tx * 4;
                if (kq + 0 > qi) wv.x = -1e30f;
                if (kq + 1 > qi) wv.y = -1e30f;
                if (kq + 2 > qi) wv.z = -1e30f;
                if (kq + 3 > qi) wv.w = -1e30f;
            }
            *(float4*)&Sc[qi * SCS + tx * 4] = wv;
        }
        __syncthreads();

        {
            float mt = -1e30f;
#pragma unroll
            for (int k = 0; k < 16; k++)
                mt = fmaxf(mt, Sc[ro * SCS + dseg + k]);
            mt = fmaxf(mt, __shfl_xor_sync(0xffffffffu, mt, 1));
            mt = fmaxf(mt, __shfl_xor_sync(0xffffffffu, mt, 2));
            float mn  = fmaxf(m_r, mt);
            float f   = __expf(m_r - mn);
            float sum = 0.f;
#pragma unroll
            for (int k = 0; k < 16; k++) {
                float pv = __expf(Sc[ro * SCS + dseg + k] - mn);
                Sc[ro * SCS + dseg + k] = pv;
                sum += pv;
            }
            sum += __shfl_xor_sync(0xffffffffu, sum, 1);
            sum += __shfl_xor_sync(0xffffffffu, sum, 2);
            l_r = l_r * f + sum;
            m_r = mn;
#pragma unroll
            for (int i = 0; i < 16; i++) o[i] *= f;
        }
        __syncthreads();

#pragma unroll 2
        for (int k = 0; k < 64; k++) {
            float  pv = Sc[ro * SCS + k];
            float4 v0 = *(const float4*)&Vt[k * 64 + dseg + 0];
            float4 v1 = *(const float4*)&Vt[k * 64 + dseg + 4];
            float4 v2 = *(const float4*)&Vt[k * 64 + dseg + 8];
            float4 v3 = *(const float4*)&Vt[k * 64 + dseg + 12];
            o[0]  = fmaf(pv, v0.x, o[0]);   o[1]  = fmaf(pv, v0.y, o[1]);
            o[2]  = fmaf(pv, v0.z, o[2]);   o[3]  = fmaf(pv, v0.w, o[3]);
            o[4]  = fmaf(pv, v1.x, o[4]);   o[5]  = fmaf(pv, v1.y, o[5]);
            o[6]  = fmaf(pv, v1.z, o[6]);   o[7]  = fmaf(pv, v1.w, o[7]);
            o[8]  = fmaf(pv, v2.x, o[8]);   o[9]  = fmaf(pv, v2.y, o[9]);
            o[10] = fmaf(pv, v2.z, o[10]);  o[11] = fmaf(pv, v2.w, o[11]);
            o[12] = fmaf(pv, v3.x, o[12]);  o[13] = fmaf(pv, v3.y, o[13]);
            o[14] = fmaf(pv, v3.z, o[14]);  o[15] = fmaf(pv, v3.w, o[15]);
        }
    }

    const float inv = 1.f / l_r;
#pragma unroll
    for (int i = 0; i < 16; i++) o[i] *= inv;
    float* dst = &g_O[(qrow0 + ro) * D_MODEL + cb + dseg];
    *(float4*)&dst[0]  = make_float4(o[0],  o[1],  o[2],  o[3]);
    *(float4*)&dst[4]  = make_float4(o[4],  o[5],  o[6],  o[7]);
    *(float4*)&dst[8]  = make_float4(o[8],  o[9],  o[10], o[11]);
    *(float4*)&dst[12] = make_float4(o[12], o[13], o[14], o[15]);
}

// ---------------------------------------------------------------------------
extern "C" void kernel_launch(void* const* d_in, const int* in_sizes, int n_in,
                              void* d_out, int out_size)
{
    (void)in_sizes; (void)n_in; (void)out_size;
    const float* query = (const float*)d_in[0];
    const float* key_  = (const float*)d_in[1];
    const float* value = (const float*)d_in[2];
    const int*   pos   = (const int*)d_in[3];
    const float* w_q   = (const float*)d_in[4];
    const float* b_q   = (const float*)d_in[5];
    const float* w_k   = (const float*)d_in[6];
    const float* b_k   = (const float*)d_in[7];
    const float* w_v   = (const float*)d_in[8];
    const float* b_v   = (const float*)d_in[9];
    const float* w_o   = (const float*)d_in[10];
    const float* b_o   = (const float*)d_in[11];
    float* out = (float*)d_out;

    float *pQ, *pK, *pV, *pO, *pWT;
    cudaGetSymbolAddress((void**)&pQ, g_Q);
    cudaGetSymbolAddress((void**)&pK, g_K);
    cudaGetSymbolAddress((void**)&pV, g_V);
    cudaGetSymbolAddress((void**)&pO, g_O);
    cudaGetSymbolAddress((void**)&pWT, g_WT);
    float* wtq = pWT + 0 * D_MODEL * D_MODEL;
    float* wtk = pWT + 1 * D_MODEL * D_MODEL;
    float* wtv = pWT + 2 * D_MODEL * D_MODEL;
    float* wto = pWT + 3 * D_MODEL * D_MODEL;

    cudaFuncSetAttribute(attn_kernel,
                         cudaFuncAttributeMaxDynamicSharedMemorySize,
                         ATTN_SMEM_BYTES);

    dim3 tgrid(32, 32), tblk(32, 8);
    transpose_kernel<<<tgrid, tblk>>>(w_q, wtq);
    transpose_kernel<<<tgrid, tblk>>>(w_k, wtk);
    transpose_kernel<<<tgrid, tblk>>>(w_v, wtv);
    transpose_kernel<<<tgrid, tblk>>>(w_o, wto);

    dim3 ggrid(D_MODEL / 128, ROWS / 128);   // (8, 64)
    gemm_tc<1><<<ggrid, 256>>>(query, wtq, b_q, pos, pQ);
    gemm_tc<1><<<ggrid, 256>>>(key_,  wtk, b_k, pos, pK);
    gemm_tc<0><<<ggrid, 256>>>(value, wtv, b_v, nullptr, pV);
    attn_kernel<<<dim3(SEQ / 64, NUM_HEADS, BATCH), 256, ATTN_SMEM_BYTES>>>();
    gemm_tc<0><<<ggrid, 256>>>(pO, wto, b_o, nullptr, out);
}

// round 8
// speedup vs baseline: 1.2938x; 1.0020x over previous
#include <cuda_runtime.h>
#include <math.h>
#include <cstdint>

#define D_MODEL   1024
#define NUM_HEADS 16
#define HEAD_DIM  64
#define BATCH     4
#define SEQ       2048
#define ROWS      (BATCH * SEQ)   // 8192

// Scratch (allocation-free rule: __device__ globals)
__device__ float g_Q[ROWS * D_MODEL];
__device__ float g_K[ROWS * D_MODEL];
__device__ float g_V[ROWS * D_MODEL];
__device__ float g_O[ROWS * D_MODEL];
__device__ float g_XC[ROWS * D_MODEL];          // tf32-rounded activation buf
__device__ float g_WT[4 * D_MODEL * D_MODEL];   // transposed+rounded weights

// ===========================================================================
// Helpers (arch-agnostic PTX only: cp.async + ldmatrix + mma.sync tf32)
// ===========================================================================
__device__ __forceinline__ uint32_t smem_u32(const void* p) {
    uint32_t a;
    asm("{ .reg .u64 t; cvta.to.shared.u64 t, %1; cvt.u32.u64 %0, t; }"
        : "=r"(a) : "l"(p));
    return a;
}
__device__ __forceinline__ void cp_async16(uint32_t dst, const void* src) {
    asm volatile("cp.async.cg.shared.global [%0], [%1], 16;"
                 :: "r"(dst), "l"(src) : "memory");
}
__device__ __forceinline__ void cp_commit() {
    asm volatile("cp.async.commit_group;" ::: "memory");
}
template <int N>
__device__ __forceinline__ void cp_wait() {
    asm volatile("cp.async.wait_group %0;" :: "n"(N) : "memory");
}
__device__ __forceinline__ float f2tf_f(float x) {
    uint32_t r;
    asm("cvt.rna.tf32.f32 %0, %1;" : "=r"(r) : "f"(x));
    return __uint_as_float(r);
}
__device__ __forceinline__ void ldsm4(uint32_t* r, uint32_t addr) {
    asm volatile("ldmatrix.sync.aligned.m8n8.x4.shared.b16 {%0,%1,%2,%3}, [%4];"
                 : "=r"(r[0]), "=r"(r[1]), "=r"(r[2]), "=r"(r[3]) : "r"(addr));
}
__device__ __forceinline__ void mma_tf32(float* c, const uint32_t* a,
                                         const uint32_t* b) {
    asm volatile(
        "mma.sync.aligned.m16n8k8.row.col.f32.tf32.tf32.f32 "
        "{%0,%1,%2,%3}, {%4,%5,%6,%7}, {%8,%9}, {%0,%1,%2,%3};"
        : "+f"(c[0]), "+f"(c[1]), "+f"(c[2]), "+f"(c[3])
        : "r"(a[0]), "r"(a[1]), "r"(a[2]), "r"(a[3]), "r"(b[0]), "r"(b[1]));
}

// ===========================================================================
// tf32 rounding pass: out[i] = round_tf32(in[i])
// ===========================================================================
__global__ void __launch_bounds__(256) cvt_tf32_kernel(
    const float* __restrict__ in, float* __restrict__ out)
{
    const size_t i = ((size_t)blockIdx.x * 256 + threadIdx.x) * 4;
    float4 v = *(const float4*)(in + i);
    v.x = f2tf_f(v.x); v.y = f2tf_f(v.y); v.z = f2tf_f(v.z); v.w = f2tf_f(v.w);
    *(float4*)(out + i) = v;
}

// ===========================================================================
// Weight transpose + tf32 round: WT[n][k] = round(W[k][n])  (1024x1024)
// ===========================================================================
__global__ void __launch_bounds__(256) transpose_kernel(
    const float* __restrict__ in, float* __restrict__ out)
{
    __shared__ float t[32][33];
    const int bx = blockIdx.x * 32, by = blockIdx.y * 32;
#pragma unroll
    for (int i = threadIdx.y; i < 32; i += 8)
        t[i][threadIdx.x] = f2tf_f(in[(size_t)(by + i) * D_MODEL + bx + threadIdx.x]);
    __syncthreads();
#pragma unroll
    for (int i = threadIdx.y; i < 32; i += 8)
        out[(size_t)(bx + i) * D_MODEL + by + threadIdx.x] = t[threadIdx.x][i];
}

// ===========================================================================
// TF32 mma.sync GEMM: out[8192,1024] = X @ W + bias (W TRANSPOSED+rounded,
// X pre-rounded), optional fused interleaved RoPE.
// CTA 128x128, BK=16, 256 threads (8 warps 2x4), warp tile 64x32.
// Double-buffered cp.async; ldmatrix.x4 fragment loads (stride-20 smem is
// conflict-free: row addrs r*20 mod 32 cover all banks).
// ===========================================================================
#define BK      16
#define SSTR    20
#define NKIT    (D_MODEL / BK)        // 64
#define BUFB    (128 * SSTR * 4)      // bytes per buffer

template <int DO_ROPE>
__global__ void __launch_bounds__(256) gemm_tc(
    const float* __restrict__ X, const float* __restrict__ WT,
    const float* __restrict__ bias, const int* __restrict__ pos,
    float* __restrict__ out)
{
    __shared__ float As[2][128 * SSTR];
    __shared__ float Bs[2][128 * SSTR];

    const int tid  = threadIdx.x;
    const int wid  = tid >> 5, lane = tid & 31;
    const int g    = lane >> 2;
    const int t    = lane & 3;
    const int row0 = blockIdx.y * 128;
    const int col0 = blockIdx.x * 128;
    const int warpM = (wid >> 2) * 64;
    const int warpN = (wid & 3) * 32;

    // ldmatrix per-lane base addresses (buffer 0, k=0)
    const int arow = lane & 15, acolh = (lane >> 4) * 4;
    uint32_t aAddr[4];
#pragma unroll
    for (int i = 0; i < 4; i++)
        aAddr[i] = smem_u32(&As[0][(warpM + i * 16 + arow) * SSTR + acolh]);
    const int brow = lane & 7, bjh = lane >> 4, bcolh = ((lane >> 3) & 1) * 4;
    uint32_t bAddr[2];
#pragma unroll
    for (int p = 0; p < 2; p++)
        bAddr[p] = smem_u32(&Bs[0][(warpN + (2 * p + bjh) * 8 + brow) * SSTR + bcolh]);

    float c[4][4][4];
#pragma unroll
    for (int i = 0; i < 4; i++)
#pragma unroll
        for (int j = 0; j < 4; j++)
#pragma unroll
            for (int q = 0; q < 4; q++) c[i][j][q] = 0.f;

    auto stage = [&](int buf, int it) {
        const float* aSrc = X  + (size_t)row0 * D_MODEL + it * BK;
        const float* bSrc = WT + (size_t)col0 * D_MODEL + it * BK;
#pragma unroll
        for (int rep = 0; rep < 2; rep++) {
            int idx = rep * 256 + tid;          // 0..511
            int r = idx >> 2, c4 = (idx & 3) * 4;
            cp_async16(smem_u32(&As[buf][r * SSTR + c4]),
                       aSrc + (size_t)r * D_MODEL + c4);
            cp_async16(smem_u32(&Bs[buf][r * SSTR + c4]),
                       bSrc + (size_t)r * D_MODEL + c4);
        }
        cp_commit();
    };

    stage(0, 0);

#pragma unroll 1
    for (int it = 0; it < NKIT; it++) {
        const int buf = it & 1;
        if (it + 1 < NKIT) {
            stage(buf ^ 1, it + 1);
            cp_wait<1>();
        } else {
            cp_wait<0>();
        }
        __syncthreads();

        const uint32_t bo = buf ? BUFB : 0;
#pragma unroll
        for (int ks = 0; ks < 2; ks++) {
            const uint32_t ko = bo + ks * 32;   // 8 floats = 32 bytes
            uint32_t af[4][4], bf[2][4];
#pragma unroll
            for (int i = 0; i < 4; i++) ldsm4(af[i], aAddr[i] + ko);
#pragma unroll
            for (int p = 0; p < 2; p++) ldsm4(bf[p], bAddr[p] + ko);
#pragma unroll
            for (int i = 0; i < 4; i++)
#pragma unroll
                for (int j = 0; j < 4; j++)
                    mma_tf32(c[i][j], af[i], &bf[j >> 1][(j & 1) * 2]);
        }
        __syncthreads();
    }

    // ---- epilogue: bias (+RoPE) in registers, float2 stores ----
    float invf[4];
    if (DO_ROPE) {
#pragma unroll
        for (int j = 0; j < 4; j++) {
            int cg = col0 + warpN + j * 8 + 2 * t;
            int ii = (cg & (HEAD_DIM - 1)) >> 1;
            invf[j] = expf(-0.287823137f * (float)ii);   // ln(1e4)/32
        }
    }
#pragma unroll
    for (int i = 0; i < 4; i++) {
        const int r0 = row0 + warpM + i * 16 + g;
        const int r1 = r0 + 8;
        float p0 = 0.f, p1 = 0.f;
        if (DO_ROPE) { p0 = (float)pos[r0]; p1 = (float)pos[r1]; }
#pragma unroll
        for (int j = 0; j < 4; j++) {
            const int cg = col0 + warpN + j * 8 + 2 * t;
            const float b0 = bias[cg], b1 = bias[cg + 1];
            float x0 = c[i][j][0] + b0, x1 = c[i][j][1] + b1;
            float y0 = c[i][j][2] + b0, y1 = c[i][j][3] + b1;
            if (DO_ROPE) {
                float sn, cs;
                sincosf(p0 * invf[j], &sn, &cs);
                float t0 = x0 * cs - x1 * sn, t1 = x0 * sn + x1 * cs;
                x0 = t0; x1 = t1;
                sincosf(p1 * invf[j], &sn, &cs);
                t0 = y0 * cs - y1 * sn; t1 = y0 * sn + y1 * cs;
                y0 = t0; y1 = t1;
            }
            *(float2*)&out[(size_t)r0 * D_MODEL + cg] = make_float2(x0, x1);
            *(float2*)&out[(size_t)r1 * D_MODEL + cg] = make_float2(y0, y1);
        }
    }
}

// ---------------------------------------------------------------------------
// Flash attention fp32, causal. Epilogue rounds O to tf32 (feeds final GEMM).
// ---------------------------------------------------------------------------
#define SCS 68
static constexpr int ATTN_SMEM_FLOATS = 64 * SCS * 3 + 64 * 64;
static constexpr int ATTN_SMEM_BYTES  = ATTN_SMEM_FLOATS * 4;

__global__ void __launch_bounds__(256) attn_kernel()
{
    extern __shared__ float smf[];
    float* Qs = smf;
    float* Kt = Qs + 64 * SCS;
    float* Sc = Kt + 64 * SCS;
    float* Vt = Sc + 64 * SCS;

    const int tid   = threadIdx.x;
    const int qtile = blockIdx.x;
    const int h     = blockIdx.y;
    const int b     = blockIdx.z;
    const int qrow0 = b * SEQ + qtile * 64;
    const int cb    = h * HEAD_DIM;

#pragma unroll
    for (int it = 0; it < 4; it++) {
        int e = it * 256 + tid;
        int r = e >> 4, c = (e & 15) * 4;
        *(float4*)&Qs[r * SCS + c] =
            *(const float4*)&g_Q[(qrow0 + r) * D_MODEL + cb + c];
    }

    const int tx   = tid & 15, ty = tid >> 4;
    const int ro   = tid >> 2;
    const int dseg = (tid & 3) * 16;

    float o[16];
#pragma unroll
    for (int i = 0; i < 16; i++) o[i] = 0.f;
    float m_r = -1e30f, l_r = 0.f;

    for (int jt = 0; jt <= qtile; jt++) {
        __syncthreads();
        const int krow0 = b * SEQ + jt * 64;
#pragma unroll
        for (int it = 0; it < 4; it++) {
            int e = it * 256 + tid;
            int r = e >> 4, c = (e & 15) * 4;
            *(float4*)&Kt[r * SCS + c] =
                *(const float4*)&g_K[(krow0 + r) * D_MODEL + cb + c];
            *(float4*)&Vt[r * 64 + c] =
                *(const float4*)&g_V[(krow0 + r) * D_MODEL + cb + c];
        }
        __syncthreads();

        float s[4][4];
#pragma unroll
        for (int i = 0; i < 4; i++)
#pragma unroll
            for (int j = 0; j < 4; j++) s[i][j] = 0.f;
#pragma unroll
        for (int d = 0; d < 64; d += 4) {
            float4 qv[4], kv[4];
#pragma unroll
            for (int i = 0; i < 4; i++)
                qv[i] = *(const float4*)&Qs[(ty * 4 + i) * SCS + d];
#pragma unroll
            for (int j = 0; j < 4; j++)
                kv[j] = *(const float4*)&Kt[(tx * 4 + j) * SCS + d];
#pragma unroll
            for (int i = 0; i < 4; i++)
#pragma unroll
                for (int j = 0; j < 4; j++) {
                    s[i][j] = fmaf(qv[i].x, kv[j].x, s[i][j]);
                    s[i][j] = fmaf(qv[i].y, kv[j].y, s[i][j]);
                    s[i][j] = fmaf(qv[i].z, kv[j].z, s[i][j]);
                    s[i][j] = fmaf(qv[i].w, kv[j].w, s[i][j]);
                }
        }
        const bool diag = (jt == qtile);
#pragma unroll
        for (int i = 0; i < 4; i++) {
            int    qi = ty * 4 + i;
            float4 wv = make_float4(s[i][0] * 0.125f, s[i][1] * 0.125f,
                                    s[i][2] * 0.125f, s[i][3] * 0.125f);
            if (diag) {
                int kq = tx * 4;
                if (kq + 0 > qi) wv.x = -1e30f;
                if (kq + 1 > qi) wv.y = -1e30f;
                if (kq + 2 > qi) wv.z = -1e30f;
                if (kq + 3 > qi) wv.w = -1e30f;
            }
            *(float4*)&Sc[qi * SCS + tx * 4] = wv;
        }
        __syncthreads();

        {
            float mt = -1e30f;
#pragma unroll
            for (int k = 0; k < 16; k++)
                mt = fmaxf(mt, Sc[ro * SCS + dseg + k]);
            mt = fmaxf(mt, __shfl_xor_sync(0xffffffffu, mt, 1));
            mt = fmaxf(mt, __shfl_xor_sync(0xffffffffu, mt, 2));
            float mn  = fmaxf(m_r, mt);
            float f   = __expf(m_r - mn);
            float sum = 0.f;
#pragma unroll
            for (int k = 0; k < 16; k++) {
                float pv = __expf(Sc[ro * SCS + dseg + k] - mn);
                Sc[ro * SCS + dseg + k] = pv;
                sum += pv;
            }
            sum += __shfl_xor_sync(0xffffffffu, sum, 1);
            sum += __shfl_xor_sync(0xffffffffu, sum, 2);
            l_r = l_r * f + sum;
            m_r = mn;
#pragma unroll
            for (int i = 0; i < 16; i++) o[i] *= f;
        }
        __syncthreads();

#pragma unroll 2
        for (int k = 0; k < 64; k++) {
            float  pv = Sc[ro * SCS + k];
            float4 v0 = *(const float4*)&Vt[k * 64 + dseg + 0];
            float4 v1 = *(const float4*)&Vt[k * 64 + dseg + 4];
            float4 v2 = *(const float4*)&Vt[k * 64 + dseg + 8];
            float4 v3 = *(const float4*)&Vt[k * 64 + dseg + 12];
            o[0]  = fmaf(pv, v0.x, o[0]);   o[1]  = fmaf(pv, v0.y, o[1]);
            o[2]  = fmaf(pv, v0.z, o[2]);   o[3]  = fmaf(pv, v0.w, o[3]);
            o[4]  = fmaf(pv, v1.x, o[4]);   o[5]  = fmaf(pv, v1.y, o[5]);
            o[6]  = fmaf(pv, v1.z, o[6]);   o[7]  = fmaf(pv, v1.w, o[7]);
            o[8]  = fmaf(pv, v2.x, o[8]);   o[9]  = fmaf(pv, v2.y, o[9]);
            o[10] = fmaf(pv, v2.z, o[10]);  o[11] = fmaf(pv, v2.w, o[11]);
            o[12] = fmaf(pv, v3.x, o[12]);  o[13] = fmaf(pv, v3.y, o[13]);
            o[14] = fmaf(pv, v3.z, o[14]);  o[15] = fmaf(pv, v3.w, o[15]);
        }
    }

    const float inv = 1.f / l_r;
#pragma unroll
    for (int i = 0; i < 16; i++) o[i] = f2tf_f(o[i] * inv);
    float* dst = &g_O[(qrow0 + ro) * D_MODEL + cb + dseg];
    *(float4*)&dst[0]  = make_float4(o[0],  o[1],  o[2],  o[3]);
    *(float4*)&dst[4]  = make_float4(o[4],  o[5],  o[6],  o[7]);
    *(float4*)&dst[8]  = make_float4(o[8],  o[9],  o[10], o[11]);
    *(float4*)&dst[12] = make_float4(o[12], o[13], o[14], o[15]);
}

// ---------------------------------------------------------------------------
extern "C" void kernel_launch(void* const* d_in, const int* in_sizes, int n_in,
                              void* d_out, int out_size)
{
    (void)in_sizes; (void)n_in; (void)out_size;
    const float* query = (const float*)d_in[0];
    const float* key_  = (const float*)d_in[1];
    const float* value = (const float*)d_in[2];
    const int*   pos   = (const int*)d_in[3];
    const float* w_q   = (const float*)d_in[4];
    const float* b_q   = (const float*)d_in[5];
    const float* w_k   = (const float*)d_in[6];
    const float* b_k   = (const float*)d_in[7];
    const float* w_v   = (const float*)d_in[8];
    const float* b_v   = (const float*)d_in[9];
    const float* w_o   = (const float*)d_in[10];
    const float* b_o   = (const float*)d_in[11];
    float* out = (float*)d_out;

    float *pQ, *pK, *pV, *pO, *pXC, *pWT;
    cudaGetSymbolAddress((void**)&pQ, g_Q);
    cudaGetSymbolAddress((void**)&pK, g_K);
    cudaGetSymbolAddress((void**)&pV, g_V);
    cudaGetSymbolAddress((void**)&pO, g_O);
    cudaGetSymbolAddress((void**)&pXC, g_XC);
    cudaGetSymbolAddress((void**)&pWT, g_WT);
    float* wtq = pWT + 0 * D_MODEL * D_MODEL;
    float* wtk = pWT + 1 * D_MODEL * D_MODEL;
    float* wtv = pWT + 2 * D_MODEL * D_MODEL;
    float* wto = pWT + 3 * D_MODEL * D_MODEL;

    cudaFuncSetAttribute(attn_kernel,
                         cudaFuncAttributeMaxDynamicSharedMemorySize,
                         ATTN_SMEM_BYTES);

    dim3 tgrid(32, 32), tblk(32, 8);
    transpose_kernel<<<tgrid, tblk>>>(w_q, wtq);
    transpose_kernel<<<tgrid, tblk>>>(w_k, wtk);
    transpose_kernel<<<tgrid, tblk>>>(w_v, wtv);
    transpose_kernel<<<tgrid, tblk>>>(w_o, wto);

    const int cvtGrid = ROWS * D_MODEL / 1024;   // 8192
    dim3 ggrid(D_MODEL / 128, ROWS / 128);       // (8, 64)

    cvt_tf32_kernel<<<cvtGrid, 256>>>(query, pXC);
    gemm_tc<1><<<ggrid, 256>>>(pXC, wtq, b_q, pos, pQ);
    cvt_tf32_kernel<<<cvtGrid, 256>>>(key_, pXC);
    gemm_tc<1><<<ggrid, 256>>>(pXC, wtk, b_k, pos, pK);
    cvt_tf32_kernel<<<cvtGrid, 256>>>(value, pXC);
    gemm_tc<0><<<ggrid, 256>>>(pXC, wtv, b_v, nullptr, pV);
    attn_kernel<<<dim3(SEQ / 64, NUM_HEADS, BATCH), 256, ATTN_SMEM_BYTES>>>();
    gemm_tc<0><<<ggrid, 256>>>(pO, wto, b_o, nullptr, out);
}

// round 10
// speedup vs baseline: 5.2291x; 4.0417x over previous
#include <cuda_runtime.h>
#include <math.h>
#include <cstdint>

#define D_MODEL   1024
#define NUM_HEADS 16
#define HEAD_DIM  64
#define BATCH     4
#define SEQ       2048
#define ROWS      (BATCH * SEQ)   // 8192

// Scratch (allocation-free rule: __device__ globals)
__device__ float g_Q[ROWS * D_MODEL];
__device__ float g_K[ROWS * D_MODEL];
__device__ float g_V[ROWS * D_MODEL];
__device__ float g_O[ROWS * D_MODEL];
__device__ float g_XC[ROWS * D_MODEL];          // tf32-rounded activation buf
__device__ float g_WT[4 * D_MODEL * D_MODEL];   // transposed+rounded weights

// ===========================================================================
// Helpers (arch-agnostic PTX only: cp.async + ldmatrix + mma.sync tf32)
// ===========================================================================
__device__ __forceinline__ uint32_t smem_u32(const void* p) {
    uint32_t a;
    asm("{ .reg .u64 t; cvta.to.shared.u64 t, %1; cvt.u32.u64 %0, t; }"
        : "=r"(a) : "l"(p));
    return a;
}
__device__ __forceinline__ void cp_async16(uint32_t dst, const void* src) {
    asm volatile("cp.async.cg.shared.global [%0], [%1], 16;"
                 :: "r"(dst), "l"(src) : "memory");
}
__device__ __forceinline__ void cp_commit() {
    asm volatile("cp.async.commit_group;" ::: "memory");
}
template <int N>
__device__ __forceinline__ void cp_wait() {
    asm volatile("cp.async.wait_group %0;" :: "n"(N) : "memory");
}
__device__ __forceinline__ float f2tf_f(float x) {
    uint32_t r;
    asm("cvt.rna.tf32.f32 %0, %1;" : "=r"(r) : "f"(x));
    return __uint_as_float(r);
}
__device__ __forceinline__ void ldsm4(uint32_t* r, uint32_t addr) {
    asm volatile("ldmatrix.sync.aligned.m8n8.x4.shared.b16 {%0,%1,%2,%3}, [%4];"
                 : "=r"(r[0]), "=r"(r[1]), "=r"(r[2]), "=r"(r[3]) : "r"(addr));
}
__device__ __forceinline__ void mma_tf32(float* c, const uint32_t* a,
                                         const uint32_t* b) {
    asm volatile(
        "mma.sync.aligned.m16n8k8.row.col.f32.tf32.tf32.f32 "
        "{%0,%1,%2,%3}, {%4,%5,%6,%7}, {%8,%9}, {%0,%1,%2,%3};"
        : "+f"(c[0]), "+f"(c[1]), "+f"(c[2]), "+f"(c[3])
        : "r"(a[0]), "r"(a[1]), "r"(a[2]), "r"(a[3]), "r"(b[0]), "r"(b[1]));
}

// ===========================================================================
// tf32 rounding pass: out[i] = round_tf32(in[i])
// ===========================================================================
__global__ void __launch_bounds__(256) cvt_tf32_kernel(
    const float* __restrict__ in, float* __restrict__ out)
{
    const size_t i = ((size_t)blockIdx.x * 256 + threadIdx.x) * 4;
    float4 v = *(const float4*)(in + i);
    v.x = f2tf_f(v.x); v.y = f2tf_f(v.y); v.z = f2tf_f(v.z); v.w = f2tf_f(v.w);
    *(float4*)(out + i) = v;
}

// ===========================================================================
// Weight transpose + tf32 round: WT[n][k] = round(W[k][n])  (1024x1024)
// ===========================================================================
__global__ void __launch_bounds__(256) transpose_kernel(
    const float* __restrict__ in, float* __restrict__ out)
{
    __shared__ float t[32][33];
    const int bx = blockIdx.x * 32, by = blockIdx.y * 32;
#pragma unroll
    for (int i = threadIdx.y; i < 32; i += 8)
        t[i][threadIdx.x] = f2tf_f(in[(size_t)(by + i) * D_MODEL + bx + threadIdx.x]);
    __syncthreads();
#pragma unroll
    for (int i = threadIdx.y; i < 32; i += 8)
        out[(size_t)(bx + i) * D_MODEL + by + threadIdx.x] = t[threadIdx.x][i];
}

// ===========================================================================
// TF32 mma.sync GEMM (proven in R7/R8): out = X @ W + bias,
// optional fused interleaved RoPE. CTA 128x128, BK=16, 8 warps, warp 64x32.
// ===========================================================================
#define BK      16
#define SSTR    20
#define NKIT    (D_MODEL / BK)        // 64
#define BUFB    (128 * SSTR * 4)      // bytes per buffer

template <int DO_ROPE>
__global__ void __launch_bounds__(256) gemm_tc(
    const float* __restrict__ X, const float* __restrict__ WT,
    const float* __restrict__ bias, const int* __restrict__ pos,
    float* __restrict__ out)
{
    __shared__ float As[2][128 * SSTR];
    __shared__ float Bs[2][128 * SSTR];

    const int tid  = threadIdx.x;
    const int wid  = tid >> 5, lane = tid & 31;
    const int g    = lane >> 2;
    const int t    = lane & 3;
    const int row0 = blockIdx.y * 128;
    const int col0 = blockIdx.x * 128;
    const int warpM = (wid >> 2) * 64;
    const int warpN = (wid & 3) * 32;

    const int arow = lane & 15, acolh = (lane >> 4) * 4;
    uint32_t aAddr[4];
#pragma unroll
    for (int i = 0; i < 4; i++)
        aAddr[i] = smem_u32(&As[0][(warpM + i * 16 + arow) * SSTR + acolh]);
    const int brow = lane & 7, bjh = lane >> 4, bcolh = ((lane >> 3) & 1) * 4;
    uint32_t bAddr[2];
#pragma unroll
    for (int p = 0; p < 2; p++)
        bAddr[p] = smem_u32(&Bs[0][(warpN + (2 * p + bjh) * 8 + brow) * SSTR + bcolh]);

    float c[4][4][4];
#pragma unroll
    for (int i = 0; i < 4; i++)
#pragma unroll
        for (int j = 0; j < 4; j++)
#pragma unroll
            for (int q = 0; q < 4; q++) c[i][j][q] = 0.f;

    auto stage = [&](int buf, int it) {
        const float* aSrc = X  + (size_t)row0 * D_MODEL + it * BK;
        const float* bSrc = WT + (size_t)col0 * D_MODEL + it * BK;
#pragma unroll
        for (int rep = 0; rep < 2; rep++) {
            int idx = rep * 256 + tid;          // 0..511
            int r = idx >> 2, c4 = (idx & 3) * 4;
            cp_async16(smem_u32(&As[buf][r * SSTR + c4]),
                       aSrc + (size_t)r * D_MODEL + c4);
            cp_async16(smem_u32(&Bs[buf][r * SSTR + c4]),
                       bSrc + (size_t)r * D_MODEL + c4);
        }
        cp_commit();
    };

    stage(0, 0);

#pragma unroll 1
    for (int it = 0; it < NKIT; it++) {
        const int buf = it & 1;
        if (it + 1 < NKIT) {
            stage(buf ^ 1, it + 1);
            cp_wait<1>();
        } else {
            cp_wait<0>();
        }
        __syncthreads();

        const uint32_t bo = buf ? BUFB : 0;
#pragma unroll
        for (int ks = 0; ks < 2; ks++) {
            const uint32_t ko = bo + ks * 32;   // 8 floats = 32 bytes
            uint32_t af[4][4], bf[2][4];
#pragma unroll
            for (int i = 0; i < 4; i++) ldsm4(af[i], aAddr[i] + ko);
#pragma unroll
            for (int p = 0; p < 2; p++) ldsm4(bf[p], bAddr[p] + ko);
#pragma unroll
            for (int i = 0; i < 4; i++)
#pragma unroll
                for (int j = 0; j < 4; j++)
                    mma_tf32(c[i][j], af[i], &bf[j >> 1][(j & 1) * 2]);
        }
        __syncthreads();
    }

    float invf[4];
    if (DO_ROPE) {
#pragma unroll
        for (int j = 0; j < 4; j++) {
            int cg = col0 + warpN + j * 8 + 2 * t;
            int ii = (cg & (HEAD_DIM - 1)) >> 1;
            invf[j] = expf(-0.287823137f * (float)ii);   // ln(1e4)/32
        }
    }
#pragma unroll
    for (int i = 0; i < 4; i++) {
        const int r0 = row0 + warpM + i * 16 + g;
        const int r1 = r0 + 8;
        float p0 = 0.f, p1 = 0.f;
        if (DO_ROPE) { p0 = (float)pos[r0]; p1 = (float)pos[r1]; }
#pragma unroll
        for (int j = 0; j < 4; j++) {
            const int cg = col0 + warpN + j * 8 + 2 * t;
            const float b0 = bias[cg], b1 = bias[cg + 1];
            float x0 = c[i][j][0] + b0, x1 = c[i][j][1] + b1;
            float y0 = c[i][j][2] + b0, y1 = c[i][j][3] + b1;
            if (DO_ROPE) {
                float sn, cs;
                sincosf(p0 * invf[j], &sn, &cs);
                float t0 = x0 * cs - x1 * sn, t1 = x0 * sn + x1 * cs;
                x0 = t0; x1 = t1;
                sincosf(p1 * invf[j], &sn, &cs);
                t0 = y0 * cs - y1 * sn; t1 = y0 * sn + y1 * cs;
                y0 = t0; y1 = t1;
            }
            *(float2*)&out[(size_t)r0 * D_MODEL + cg] = make_float2(x0, x1);
            *(float2*)&out[(size_t)r1 * D_MODEL + cg] = make_float2(y0, y1);
        }
    }
}

// ===========================================================================
// Flash attention, causal — tf32 mma.sync for BOTH S=QK^T and O=PV.
// 128 threads (4 warps), each warp owns 16 q-rows. 64x64 k-tiles.
// Q/K/V/P tf32-rounded at smem store; online softmax on C-fragments.
// ===========================================================================
#define ASTR 68
static constexpr int ATTN_SMEM_BYTES = 4 * 64 * ASTR * 4;   // 69632

__global__ void __launch_bounds__(128) attn_kernel()
{
    extern __shared__ float smf[];
    float* Qs = smf;                 // [64][ASTR]  (pre-scaled by 0.125)
    float* Ks = Qs + 64 * ASTR;
    float* Vs = Ks + 64 * ASTR;
    float* Ps = Vs + 64 * ASTR;      // per-warp 16-row regions

    const int tid   = threadIdx.x;
    const int w     = tid >> 5, lane = tid & 31;
    const int g     = lane >> 2, t = lane & 3;
    const int qtile = blockIdx.x;
    const int h     = blockIdx.y;
    const int b     = blockIdx.z;
    const int qrow0 = b * SEQ + qtile * 64;
    const int cb    = h * HEAD_DIM;

    // ---- load Q tile (scaled by 1/8 = exact, tf32-rounded) ----
#pragma unroll
    for (int itr = 0; itr < 8; itr++) {
        int e = itr * 128 + tid;             // 0..1023 float4 slots
        int r = e >> 4, c = (e & 15) * 4;
        float4 v = *(const float4*)&g_Q[(size_t)(qrow0 + r) * D_MODEL + cb + c];
        v.x = f2tf_f(v.x * 0.125f); v.y = f2tf_f(v.y * 0.125f);
        v.z = f2tf_f(v.z * 0.125f); v.w = f2tf_f(v.w * 0.125f);
        *(float4*)&Qs[r * ASTR + c] = v;
    }

    // fragment base addresses
    const uint32_t aQ = smem_u32(&Qs[(w * 16 + (lane & 15)) * ASTR + (lane >> 4) * 4]);
    const uint32_t aP = smem_u32(&Ps[(w * 16 + (lane & 15)) * ASTR + (lane >> 4) * 4]);
    uint32_t bK[4];
#pragma unroll
    for (int p = 0; p < 4; p++)
        bK[p] = smem_u32(&Ks[((2 * p + (lane >> 4)) * 8 + (lane & 7)) * ASTR +
                             ((lane >> 3) & 1) * 4]);

    float cO[8][4];
#pragma unroll
    for (int j = 0; j < 8; j++)
#pragma unroll
        for (int q = 0; q < 4; q++) cO[j][q] = 0.f;
    float m0 = -1e30f, m1 = -1e30f, l0 = 0.f, l1 = 0.f;

    const int q0 = w * 16 + g;      // local q row of fragment row 0
    const int q1 = q0 + 8;

#pragma unroll 1
    for (int kt = 0; kt <= qtile; kt++) {
        __syncthreads();   // everyone done reading Ks/Vs from previous iter
        const int krow0 = b * SEQ + kt * 64;
#pragma unroll
        for (int itr = 0; itr < 8; itr++) {
            int e = itr * 128 + tid;
            int r = e >> 4, c = (e & 15) * 4;
            float4 kv = *(const float4*)&g_K[(size_t)(krow0 + r) * D_MODEL + cb + c];
            kv.x = f2tf_f(kv.x); kv.y = f2tf_f(kv.y);
            kv.z = f2tf_f(kv.z); kv.w = f2tf_f(kv.w);
            *(float4*)&Ks[r * ASTR + c] = kv;
            float4 vv = *(const float4*)&g_V[(size_t)(krow0 + r) * D_MODEL + cb + c];
            vv.x = f2tf_f(vv.x); vv.y = f2tf_f(vv.y);
            vv.z = f2tf_f(vv.z); vv.w = f2tf_f(vv.w);
            *(float4*)&Vs[r * ASTR + c] = vv;
        }
        __syncthreads();

        // ---- S = (Q/8) @ K^T ----
        float cS[8][4];
#pragma unroll
        for (int j = 0; j < 8; j++)
#pragma unroll
            for (int q = 0; q < 4; q++) cS[j][q] = 0.f;
#pragma unroll
        for (int ks = 0; ks < 8; ks++) {
            uint32_t af[4], bf[4][4];
            ldsm4(af, aQ + ks * 32);
#pragma unroll
            for (int p = 0; p < 4; p++) ldsm4(bf[p], bK[p] + ks * 32);
#pragma unroll
            for (int j = 0; j < 8; j++)
                mma_tf32(cS[j], af, &bf[j >> 1][(j & 1) * 2]);
        }

        // ---- causal mask on diagonal tile ----
        if (kt == qtile) {
#pragma unroll
            for (int j = 0; j < 8; j++) {
                int kp = j * 8 + 2 * t;
                if (kp     > q0) cS[j][0] = -1e30f;
                if (kp + 1 > q0) cS[j][1] = -1e30f;
                if (kp     > q1) cS[j][2] = -1e30f;
                if (kp + 1 > q1) cS[j][3] = -1e30f;
            }
        }

        // ---- online softmax (quad reductions; 2 rows per thread) ----
        float mt0 = -1e30f, mt1 = -1e30f;
#pragma unroll
        for (int j = 0; j < 8; j++) {
            mt0 = fmaxf(mt0, fmaxf(cS[j][0], cS[j][1]));
            mt1 = fmaxf(mt1, fmaxf(cS[j][2], cS[j][3]));
        }
        mt0 = fmaxf(mt0, __shfl_xor_sync(0xffffffffu, mt0, 1));
        mt0 = fmaxf(mt0, __shfl_xor_sync(0xffffffffu, mt0, 2));
        mt1 = fmaxf(mt1, __shfl_xor_sync(0xffffffffu, mt1, 1));
        mt1 = fmaxf(mt1, __shfl_xor_sync(0xffffffffu, mt1, 2));
        const float mn0 = fmaxf(m0, mt0), mn1 = fmaxf(m1, mt1);
        const float f0 = __expf(m0 - mn0), f1 = __expf(m1 - mn1);
        float s0 = 0.f, s1 = 0.f;
#pragma unroll
        for (int j = 0; j < 8; j++) {
            cS[j][0] = __expf(cS[j][0] - mn0); s0 += cS[j][0];
            cS[j][1] = __expf(cS[j][1] - mn0); s0 += cS[j][1];
            cS[j][2] = __expf(cS[j][2] - mn1); s1 += cS[j][2];
            cS[j][3] = __expf(cS[j][3] - mn1); s1 += cS[j][3];
        }
        s0 += __shfl_xor_sync(0xffffffffu, s0, 1);
        s0 += __shfl_xor_sync(0xffffffffu, s0, 2);
        s1 += __shfl_xor_sync(0xffffffffu, s1, 1);
        s1 += __shfl_xor_sync(0xffffffffu, s1, 2);
        l0 = l0 * f0 + s0;  l1 = l1 * f1 + s1;
        m0 = mn0;           m1 = mn1;
#pragma unroll
        for (int j = 0; j < 8; j++) {
            cO[j][0] *= f0; cO[j][1] *= f0;
            cO[j][2] *= f1; cO[j][3] *= f1;
        }

        // ---- store P to per-warp smem region (tf32-rounded) ----
#pragma unroll
        for (int j = 0; j < 8; j++) {
            *(float2*)&Ps[q0 * ASTR + j * 8 + 2 * t] =
                make_float2(f2tf_f(cS[j][0]), f2tf_f(cS[j][1]));
            *(float2*)&Ps[q1 * ASTR + j * 8 + 2 * t] =
                make_float2(f2tf_f(cS[j][2]), f2tf_f(cS[j][3]));
        }
        __syncwarp();

        // ---- O += P @ V  (B fragments: scalar LDS from row-major Vs) ----
#pragma unroll
        for (int ks = 0; ks < 8; ks++) {
            uint32_t ap[4];
            ldsm4(ap, aP + ks * 32);
            const float* vb = &Vs[(ks * 8 + t) * ASTR + g];
#pragma unroll
            for (int j = 0; j < 8; j++) {
                uint32_t bv[2];
                bv[0] = __float_as_uint(vb[j * 8]);
                bv[1] = __float_as_uint(vb[4 * ASTR + j * 8]);
                mma_tf32(cO[j], ap, bv);
            }
        }
    }

    // ---- epilogue: normalize, round tf32 (feeds final GEMM), store ----
    const float inv0 = 1.f / l0, inv1 = 1.f / l1;
    float* dst0 = &g_O[(size_t)(qrow0 + q0) * D_MODEL + cb];
    float* dst1 = &g_O[(size_t)(qrow0 + q1) * D_MODEL + cb];
#pragma unroll
    for (int j = 0; j < 8; j++) {
        *(float2*)&dst0[j * 8 + 2 * t] =
            make_float2(f2tf_f(cO[j][0] * inv0), f2tf_f(cO[j][1] * inv0));
        *(float2*)&dst1[j * 8 + 2 * t] =
            make_float2(f2tf_f(cO[j][2] * inv1), f2tf_f(cO[j][3] * inv1));
    }
}

// ---------------------------------------------------------------------------
extern "C" void kernel_launch(void* const* d_in, const int* in_sizes, int n_in,
                              void* d_out, int out_size)
{
    (void)in_sizes; (void)n_in; (void)out_size;
    const float* query = (const float*)d_in[0];
    const float* key_  = (const float*)d_in[1];
    const float* value = (const float*)d_in[2];
    const int*   pos   = (const int*)d_in[3];
    const float* w_q   = (const float*)d_in[4];
    const float* b_q   = (const float*)d_in[5];
    const float* w_k   = (const float*)d_in[6];
    const float* b_k   = (const float*)d_in[7];
    const float* w_v   = (const float*)d_in[8];
    const float* b_v   = (const float*)d_in[9];
    const float* w_o   = (const float*)d_in[10];
    const float* b_o   = (const float*)d_in[11];
    float* out = (float*)d_out;

    float *pQ, *pK, *pV, *pO, *pXC, *pWT;
    cudaGetSymbolAddress((void**)&pQ, g_Q);
    cudaGetSymbolAddress((void**)&pK, g_K);
    cudaGetSymbolAddress((void**)&pV, g_V);
    cudaGetSymbolAddress((void**)&pO, g_O);
    cudaGetSymbolAddress((void**)&pXC, g_XC);
    cudaGetSymbolAddress((void**)&pWT, g_WT);
    float* wtq = pWT + 0 * D_MODEL * D_MODEL;
    float* wtk = pWT + 1 * D_MODEL * D_MODEL;
    float* wtv = pWT + 2 * D_MODEL * D_MODEL;
    float* wto = pWT + 3 * D_MODEL * D_MODEL;

    cudaFuncSetAttribute(attn_kernel,
                         cudaFuncAttributeMaxDynamicSharedMemorySize,
                         ATTN_SMEM_BYTES);

    dim3 tgrid(32, 32), tblk(32, 8);
    transpose_kernel<<<tgrid, tblk>>>(w_q, wtq);
    transpose_kernel<<<tgrid, tblk>>>(w_k, wtk);
    transpose_kernel<<<tgrid, tblk>>>(w_v, wtv);
    transpose_kernel<<<tgrid, tblk>>>(w_o, wto);

    const int cvtGrid = ROWS * D_MODEL / 1024;   // 8192
    dim3 ggrid(D_MODEL / 128, ROWS / 128);       // (8, 64)

    cvt_tf32_kernel<<<cvtGrid, 256>>>(query, pXC);
    gemm_tc<1><<<ggrid, 256>>>(pXC, wtq, b_q, pos, pQ);
    cvt_tf32_kernel<<<cvtGrid, 256>>>(key_, pXC);
    gemm_tc<1><<<ggrid, 256>>>(pXC, wtk, b_k, pos, pK);
    cvt_tf32_kernel<<<cvtGrid, 256>>>(value, pXC);
    gemm_tc<0><<<ggrid, 256>>>(pXC, wtv, b_v, nullptr, pV);
    attn_kernel<<<dim3(SEQ / 64, NUM_HEADS, BATCH), 128, ATTN_SMEM_BYTES>>>();
    gemm_tc<0><<<ggrid, 256>>>(pO, wto, b_o, nullptr, out);
}

// round 13
// speedup vs baseline: 5.5296x; 1.0575x over previous
#include <cuda_runtime.h>
#include <math.h>
#include <cstdint>

#define D_MODEL   1024
#define NUM_HEADS 16
#define HEAD_DIM  64
#define BATCH     4
#define SEQ       2048
#define ROWS      (BATCH * SEQ)   // 8192

// Scratch (allocation-free rule: __device__ globals)
__device__ float g_Q[ROWS * D_MODEL];
__device__ float g_K[ROWS * D_MODEL];
__device__ float g_V[ROWS * D_MODEL];
__device__ float g_O[ROWS * D_MODEL];
__device__ float g_WT[4 * D_MODEL * D_MODEL];   // transposed+rounded weights

// ===========================================================================
// Helpers (arch-agnostic PTX only: cp.async + ldmatrix + mma.sync tf32)
// ===========================================================================
__device__ __forceinline__ uint32_t smem_u32(const void* p) {
    uint32_t a;
    asm("{ .reg .u64 t; cvta.to.shared.u64 t, %1; cvt.u32.u64 %0, t; }"
        : "=r"(a) : "l"(p));
    return a;
}
__device__ __forceinline__ void cp_async16(uint32_t dst, const void* src) {
    asm volatile("cp.async.cg.shared.global [%0], [%1], 16;"
                 :: "r"(dst), "l"(src) : "memory");
}
__device__ __forceinline__ void cp_commit() {
    asm volatile("cp.async.commit_group;" ::: "memory");
}
template <int N>
__device__ __forceinline__ void cp_wait() {
    asm volatile("cp.async.wait_group %0;" :: "n"(N) : "memory");
}
__device__ __forceinline__ float f2tf_f(float x) {
    uint32_t r;
    asm("cvt.rna.tf32.f32 %0, %1;" : "=r"(r) : "f"(x));
    return __uint_as_float(r);
}
__device__ __forceinline__ uint32_t f2tf_u(uint32_t x) {
    uint32_t r;
    asm("cvt.rna.tf32.f32 %0, %1;" : "=r"(r) : "r"(x));
    return r;
}
__device__ __forceinline__ void ldsm4(uint32_t* r, uint32_t addr) {
    asm volatile("ldmatrix.sync.aligned.m8n8.x4.shared.b16 {%0,%1,%2,%3}, [%4];"
                 : "=r"(r[0]), "=r"(r[1]), "=r"(r[2]), "=r"(r[3]) : "r"(addr));
}
__device__ __forceinline__ void mma_tf32(float* c, const uint32_t* a,
                                         const uint32_t* b) {
    asm volatile(
        "mma.sync.aligned.m16n8k8.row.col.f32.tf32.tf32.f32 "
        "{%0,%1,%2,%3}, {%4,%5,%6,%7}, {%8,%9}, {%0,%1,%2,%3};"
        : "+f"(c[0]), "+f"(c[1]), "+f"(c[2]), "+f"(c[3])
        : "r"(a[0]), "r"(a[1]), "r"(a[2]), "r"(a[3]), "r"(b[0]), "r"(b[1]));
}

// ===========================================================================
// Fused weight transpose + tf32 round: WT_z[n][k] = round(W_z[k][n]), z=0..3
// ===========================================================================
__global__ void __launch_bounds__(256) transpose_kernel(
    const float* __restrict__ w0, const float* __restrict__ w1,
    const float* __restrict__ w2, const float* __restrict__ w3,
    float* __restrict__ outbase)
{
    __shared__ float t[32][33];
    const int z = blockIdx.z;
    const float* in = (z == 0) ? w0 : (z == 1) ? w1 : (z == 2) ? w2 : w3;
    float* out = outbase + (size_t)z * D_MODEL * D_MODEL;
    const int bx = blockIdx.x * 32, by = blockIdx.y * 32;
#pragma unroll
    for (int i = threadIdx.y; i < 32; i += 8)
        t[i][threadIdx.x] = f2tf_f(in[(size_t)(by + i) * D_MODEL + bx + threadIdx.x]);
    __syncthreads();
#pragma unroll
    for (int i = threadIdx.y; i < 32; i += 8)
        out[(size_t)(bx + i) * D_MODEL + by + threadIdx.x] = t[threadIdx.x][i];
}

// ===========================================================================
// TF32 mma.sync GEMM core (proven R7-R10). CTA 128x128, BK=16, 8 warps,
// warp 64x32, double-buffered cp.async, ldmatrix fragments.
// DO_CVT: round A-fragments in-loop (for raw fp32 activations).
// ===========================================================================
#define BK      16
#define SSTR    20
#define NKIT    (D_MODEL / BK)        // 64
#define BUFB    (128 * SSTR * 4)      // bytes per buffer

template <int DO_CVT>
__device__ __forceinline__ void gemm_body(
    const float* __restrict__ X, const float* __restrict__ WT,
    const float* __restrict__ bias, const int* __restrict__ pos,
    float* __restrict__ out, bool do_rope,
    float (*As)[128 * SSTR], float (*Bs)[128 * SSTR],
    int row0, int col0)
{
    const int tid  = threadIdx.x;
    const int wid  = tid >> 5, lane = tid & 31;
    const int g    = lane >> 2;
    const int t    = lane & 3;
    const int warpM = (wid >> 2) * 64;
    const int warpN = (wid & 3) * 32;

    const int arow = lane & 15, acolh = (lane >> 4) * 4;
    uint32_t aAddr[4];
#pragma unroll
    for (int i = 0; i < 4; i++)
        aAddr[i] = smem_u32(&As[0][(warpM + i * 16 + arow) * SSTR + acolh]);
    const int brow = lane & 7, bjh = lane >> 4, bcolh = ((lane >> 3) & 1) * 4;
    uint32_t bAddr[2];
#pragma unroll
    for (int p = 0; p < 2; p++)
        bAddr[p] = smem_u32(&Bs[0][(warpN + (2 * p + bjh) * 8 + brow) * SSTR + bcolh]);

    float c[4][4][4];
#pragma unroll
    for (int i = 0; i < 4; i++)
#pragma unroll
        for (int j = 0; j < 4; j++)
#pragma unroll
            for (int q = 0; q < 4; q++) c[i][j][q] = 0.f;

    auto stage = [&](int buf, int it) {
        const float* aSrc = X  + (size_t)row0 * D_MODEL + it * BK;
        const float* bSrc = WT + (size_t)col0 * D_MODEL + it * BK;
#pragma unroll
        for (int rep = 0; rep < 2; rep++) {
            int idx = rep * 256 + tid;          // 0..511
            int r = idx >> 2, c4 = (idx & 3) * 4;
            cp_async16(smem_u32(&As[buf][r * SSTR + c4]),
                       aSrc + (size_t)r * D_MODEL + c4);
            cp_async16(smem_u32(&Bs[buf][r * SSTR + c4]),
                       bSrc + (size_t)r * D_MODEL + c4);
        }
        cp_commit();
    };

    stage(0, 0);

#pragma unroll 1
    for (int it = 0; it < NKIT; it++) {
        const int buf = it & 1;
        if (it + 1 < NKIT) {
            stage(buf ^ 1, it + 1);
            cp_wait<1>();
        } else {
            cp_wait<0>();
        }
        __syncthreads();

        const uint32_t bo = buf ? BUFB : 0;
#pragma unroll
        for (int ks = 0; ks < 2; ks++) {
            const uint32_t ko = bo + ks * 32;   // 8 floats = 32 bytes
            uint32_t af[4][4], bf[2][4];
#pragma unroll
            for (int i = 0; i < 4; i++) ldsm4(af[i], aAddr[i] + ko);
#pragma unroll
            for (int p = 0; p < 2; p++) ldsm4(bf[p], bAddr[p] + ko);
            if (DO_CVT) {
#pragma unroll
                for (int i = 0; i < 4; i++)
#pragma unroll
                    for (int q = 0; q < 4; q++) af[i][q] = f2tf_u(af[i][q]);
            }
#pragma unroll
            for (int i = 0; i < 4; i++)
#pragma unroll
                for (int j = 0; j < 4; j++)
                    mma_tf32(c[i][j], af[i], &bf[j >> 1][(j & 1) * 2]);
        }
        __syncthreads();
    }

    float invf[4];
    if (do_rope) {
#pragma unroll
        for (int j = 0; j < 4; j++) {
            int cg = col0 + warpN + j * 8 + 2 * t;
            int ii = (cg & (HEAD_DIM - 1)) >> 1;
            invf[j] = expf(-0.287823137f * (float)ii);   // ln(1e4)/32
        }
    }
#pragma unroll
    for (int i = 0; i < 4; i++) {
        const int r0 = row0 + warpM + i * 16 + g;
        const int r1 = r0 + 8;
        float p0 = 0.f, p1 = 0.f;
        if (do_rope) { p0 = (float)pos[r0]; p1 = (float)pos[r1]; }
#pragma unroll
        for (int j = 0; j < 4; j++) {
            const int cg = col0 + warpN + j * 8 + 2 * t;
            const float b0 = bias[cg], b1 = bias[cg + 1];
            float x0 = c[i][j][0] + b0, x1 = c[i][j][1] + b1;
            float y0 = c[i][j][2] + b0, y1 = c[i][j][3] + b1;
            if (do_rope) {
                float sn, cs;
                sincosf(p0 * invf[j], &sn, &cs);
                float t0 = x0 * cs - x1 * sn, t1 = x0 * sn + x1 * cs;
                x0 = t0; x1 = t1;
                sincosf(p1 * invf[j], &sn, &cs);
                t0 = y0 * cs - y1 * sn; t1 = y0 * sn + y1 * cs;
                y0 = t0; y1 = t1;
            }
            *(float2*)&out[(size_t)r0 * D_MODEL + cg] = make_float2(x0, x1);
            *(float2*)&out[(size_t)r1 * D_MODEL + cg] = make_float2(y0, y1);
        }
    }
}

// Fused Q/K/V projection: grid.z selects input/weight/bias/output.
__global__ void __launch_bounds__(256) gemm_qkv(
    const float* __restrict__ query, const float* __restrict__ key_,
    const float* __restrict__ value, const float* __restrict__ wtbase,
    const float* __restrict__ b_q, const float* __restrict__ b_k,
    const float* __restrict__ b_v, const int* __restrict__ pos,
    float* __restrict__ oQ, float* __restrict__ oK, float* __restrict__ oV)
{
    __shared__ float As[2][128 * SSTR];
    __shared__ float Bs[2][128 * SSTR];
    const int z = blockIdx.z;
    const float* X    = (z == 0) ? query : (z == 1) ? key_ : value;
    const float* WT   = wtbase + (size_t)z * D_MODEL * D_MODEL;
    const float* bias = (z == 0) ? b_q : (z == 1) ? b_k : b_v;
    float* out        = (z == 0) ? oQ : (z == 1) ? oK : oV;
    gemm_body<1>(X, WT, bias, pos, out, z < 2, As, Bs,
                 blockIdx.y * 128, blockIdx.x * 128);
}

// Output projection: A (g_O) is already tf32-rounded by attention.
__global__ void __launch_bounds__(256) gemm_o(
    const float* __restrict__ X, const float* __restrict__ WT,
    const float* __restrict__ bias, float* __restrict__ out)
{
    __shared__ float As[2][128 * SSTR];
    __shared__ float Bs[2][128 * SSTR];
    gemm_body<0>(X, WT, bias, nullptr, out, false, As, Bs,
                 blockIdx.y * 128, blockIdx.x * 128);
}

// ===========================================================================
// Flash attention, causal — tf32 mma.sync for BOTH S=QK^T and O=PV.
// (proven R10) 128 threads (4 warps), each warp owns 16 q-rows. 64x64 tiles.
// ===========================================================================
#define ASTR 68
static constexpr int ATTN_SMEM_BYTES = 4 * 64 * ASTR * 4;   // 69632

__global__ void __launch_bounds__(128) attn_kernel()
{
    extern __shared__ float smf[];
    float* Qs = smf;                 // [64][ASTR]  (pre-scaled by 0.125)
    float* Ks = Qs + 64 * ASTR;
    float* Vs = Ks + 64 * ASTR;
    float* Ps = Vs + 64 * ASTR;      // per-warp 16-row regions

    const int tid   = threadIdx.x;
    const int w     = tid >> 5, lane = tid & 31;
    const int g     = lane >> 2, t = lane & 3;
    const int qtile = blockIdx.x;
    const int h     = blockIdx.y;
    const int b     = blockIdx.z;
    const int qrow0 = b * SEQ + qtile * 64;
    const int cb    = h * HEAD_DIM;

    // ---- load Q tile (scaled by 1/8 = exact, tf32-rounded) ----
#pragma unroll
    for (int itr = 0; itr < 8; itr++) {
        int e = itr * 128 + tid;             // 0..1023 float4 slots
        int r = e >> 4, c = (e & 15) * 4;
        float4 v = *(const float4*)&g_Q[(size_t)(qrow0 + r) * D_MODEL + cb + c];
        v.x = f2tf_f(v.x * 0.125f); v.y = f2tf_f(v.y * 0.125f);
        v.z = f2tf_f(v.z * 0.125f); v.w = f2tf_f(v.w * 0.125f);
        *(float4*)&Qs[r * ASTR + c] = v;
    }

    const uint32_t aQ = smem_u32(&Qs[(w * 16 + (lane & 15)) * ASTR + (lane >> 4) * 4]);
    const uint32_t aP = smem_u32(&Ps[(w * 16 + (lane & 15)) * ASTR + (lane >> 4) * 4]);
    uint32_t bK[4];
#pragma unroll
    for (int p = 0; p < 4; p++)
        bK[p] = smem_u32(&Ks[((2 * p + (lane >> 4)) * 8 + (lane & 7)) * ASTR +
                             ((lane >> 3) & 1) * 4]);

    float cO[8][4];
#pragma unroll
    for (int j = 0; j < 8; j++)
#pragma unroll
        for (int q = 0; q < 4; q++) cO[j][q] = 0.f;
    float m0 = -1e30f, m1 = -1e30f, l0 = 0.f, l1 = 0.f;

    const int q0 = w * 16 + g;
    const int q1 = q0 + 8;

#pragma unroll 1
    for (int kt = 0; kt <= qtile; kt++) {
        __syncthreads();
        const int krow0 = b * SEQ + kt * 64;
#pragma unroll
        for (int itr = 0; itr < 8; itr++) {
            int e = itr * 128 + tid;
            int r = e >> 4, c = (e & 15) * 4;
            float4 kv = *(const float4*)&g_K[(size_t)(krow0 + r) * D_MODEL + cb + c];
            kv.x = f2tf_f(kv.x); kv.y = f2tf_f(kv.y);
            kv.z = f2tf_f(kv.z); kv.w = f2tf_f(kv.w);
            *(float4*)&Ks[r * ASTR + c] = kv;
            float4 vv = *(const float4*)&g_V[(size_t)(krow0 + r) * D_MODEL + cb + c];
            vv.x = f2tf_f(vv.x); vv.y = f2tf_f(vv.y);
            vv.z = f2tf_f(vv.z); vv.w = f2tf_f(vv.w);
            *(float4*)&Vs[r * ASTR + c] = vv;
        }
        __syncthreads();

        // ---- S = (Q/8) @ K^T ----
        float cS[8][4];
#pragma unroll
        for (int j = 0; j < 8; j++)
#pragma unroll
            for (int q = 0; q < 4; q++) cS[j][q] = 0.f;
#pragma unroll
        for (int ks = 0; ks < 8; ks++) {
            uint32_t af[4], bf[4][4];
            ldsm4(af, aQ + ks * 32);
#pragma unroll
            for (int p = 0; p < 4; p++) ldsm4(bf[p], bK[p] + ks * 32);
#pragma unroll
            for (int j = 0; j < 8; j++)
                mma_tf32(cS[j], af, &bf[j >> 1][(j & 1) * 2]);
        }

        if (kt == qtile) {
#pragma unroll
            for (int j = 0; j < 8; j++) {
                int kp = j * 8 + 2 * t;
                if (kp     > q0) cS[j][0] = -1e30f;
                if (kp + 1 > q0) cS[j][1] = -1e30f;
                if (kp     > q1) cS[j][2] = -1e30f;
                if (kp + 1 > q1) cS[j][3] = -1e30f;
            }
        }

        // ---- online softmax ----
        float mt0 = -1e30f, mt1 = -1e30f;
#pragma unroll
        for (int j = 0; j < 8; j++) {
            mt0 = fmaxf(mt0, fmaxf(cS[j][0], cS[j][1]));
            mt1 = fmaxf(mt1, fmaxf(cS[j][2], cS[j][3]));
        }
        mt0 = fmaxf(mt0, __shfl_xor_sync(0xffffffffu, mt0, 1));
        mt0 = fmaxf(mt0, __shfl_xor_sync(0xffffffffu, mt0, 2));
        mt1 = fmaxf(mt1, __shfl_xor_sync(0xffffffffu, mt1, 1));
        mt1 = fmaxf(mt1, __shfl_xor_sync(0xffffffffu, mt1, 2));
        const float mn0 = fmaxf(m0, mt0), mn1 = fmaxf(m1, mt1);
        const float f0 = __expf(m0 - mn0), f1 = __expf(m1 - mn1);
        float s0 = 0.f, s1 = 0.f;
#pragma unroll
        for (int j = 0; j < 8; j++) {
            cS[j][0] = __expf(cS[j][0] - mn0); s0 += cS[j][0];
            cS[j][1] = __expf(cS[j][1] - mn0); s0 += cS[j][1];
            cS[j][2] = __expf(cS[j][2] - mn1); s1 += cS[j][2];
            cS[j][3] = __expf(cS[j][3] - mn1); s1 += cS[j][3];
        }
        s0 += __shfl_xor_sync(0xffffffffu, s0, 1);
        s0 += __shfl_xor_sync(0xffffffffu, s0, 2);
        s1 += __shfl_xor_sync(0xffffffffu, s1, 1);
        s1 += __shfl_xor_sync(0xffffffffu, s1, 2);
        l0 = l0 * f0 + s0;  l1 = l1 * f1 + s1;
        m0 = mn0;           m1 = mn1;
#pragma unroll
        for (int j = 0; j < 8; j++) {
            cO[j][0] *= f0; cO[j][1] *= f0;
            cO[j][2] *= f1; cO[j][3] *= f1;
        }

        // ---- P to per-warp smem (tf32-rounded) ----
#pragma unroll
        for (int j = 0; j < 8; j++) {
            *(float2*)&Ps[q0 * ASTR + j * 8 + 2 * t] =
                make_float2(f2tf_f(cS[j][0]), f2tf_f(cS[j][1]));
            *(float2*)&Ps[q1 * ASTR + j * 8 + 2 * t] =
                make_float2(f2tf_f(cS[j][2]), f2tf_f(cS[j][3]));
        }
        __syncwarp();

        // ---- O += P @ V ----
#pragma unroll
        for (int ks = 0; ks < 8; ks++) {
            uint32_t ap[4];
            ldsm4(ap, aP + ks * 32);
            const float* vb = &Vs[(ks * 8 + t) * ASTR + g];
#pragma unroll
            for (int j = 0; j < 8; j++) {
                uint32_t bv[2];
                bv[0] = __float_as_uint(vb[j * 8]);
                bv[1] = __float_as_uint(vb[4 * ASTR + j * 8]);
                mma_tf32(cO[j], ap, bv);
            }
        }
    }

    // ---- epilogue ----
    const float inv0 = 1.f / l0, inv1 = 1.f / l1;
    float* dst0 = &g_O[(size_t)(qrow0 + q0) * D_MODEL + cb];
    float* dst1 = &g_O[(size_t)(qrow0 + q1) * D_MODEL + cb];
#pragma unroll
    for (int j = 0; j < 8; j++) {
        *(float2*)&dst0[j * 8 + 2 * t] =
            make_float2(f2tf_f(cO[j][0] * inv0), f2tf_f(cO[j][1] * inv0));
        *(float2*)&dst1[j * 8 + 2 * t] =
            make_float2(f2tf_f(cO[j][2] * inv1), f2tf_f(cO[j][3] * inv1));
    }
}

// ---------------------------------------------------------------------------
extern "C" void kernel_launch(void* const* d_in, const int* in_sizes, int n_in,
                              void* d_out, int out_size)
{
    (void)in_sizes; (void)n_in; (void)out_size;
    const float* query = (const float*)d_in[0];
    const float* key_  = (const float*)d_in[1];
    const float* value = (const float*)d_in[2];
    const int*   pos   = (const int*)d_in[3];
    const float* w_q   = (const float*)d_in[4];
    const float* b_q   = (const float*)d_in[5];
    const float* w_k   = (const float*)d_in[6];
    const float* b_k   = (const float*)d_in[7];
    const float* w_v   = (const float*)d_in[8];
    const float* b_v   = (const float*)d_in[9];
    const float* w_o   = (const float*)d_in[10];
    const float* b_o   = (const float*)d_in[11];
    float* out = (float*)d_out;

    float *pQ, *pK, *pV, *pO, *pWT;
    cudaGetSymbolAddress((void**)&pQ, g_Q);
    cudaGetSymbolAddress((void**)&pK, g_K);
    cudaGetSymbolAddress((void**)&pV, g_V);
    cudaGetSymbolAddress((void**)&pO, g_O);
    cudaGetSymbolAddress((void**)&pWT, g_WT);
    float* wto = pWT + 3 * (size_t)D_MODEL * D_MODEL;

    cudaFuncSetAttribute(attn_kernel,
                         cudaFuncAttributeMaxDynamicSharedMemorySize,
                         ATTN_SMEM_BYTES);

    transpose_kernel<<<dim3(32, 32, 4), dim3(32, 8)>>>(w_q, w_k, w_v, w_o, pWT);

    gemm_qkv<<<dim3(D_MODEL / 128, ROWS / 128, 3), 256>>>(
        query, key_, value, pWT, b_q, b_k, b_v, pos, pQ, pK, pV);

    attn_kernel<<<dim3(SEQ / 64, NUM_HEADS, BATCH), 128, ATTN_SMEM_BYTES>>>();

    gemm_o<<<dim3(D_MODEL / 128, ROWS / 128), 256>>>(pO, wto, b_o, out);
}

// round 14
// speedup vs baseline: 5.5857x; 1.0101x over previous
#include <cuda_runtime.h>
#include <math.h>
#include <cstdint>

#define D_MODEL   1024
#define NUM_HEADS 16
#define HEAD_DIM  64
#define BATCH     4
#define SEQ       2048
#define ROWS      (BATCH * SEQ)   // 8192

// Scratch (allocation-free rule: __device__ globals)
__device__ float g_Q[ROWS * D_MODEL];
__device__ float g_K[ROWS * D_MODEL];
__device__ float g_V[ROWS * D_MODEL];
__device__ float g_O[ROWS * D_MODEL];
__device__ float g_WT[4 * D_MODEL * D_MODEL];   // transposed+rounded weights

// ===========================================================================
// Helpers (arch-agnostic PTX only: cp.async + ldmatrix + mma.sync tf32)
// ===========================================================================
__device__ __forceinline__ uint32_t smem_u32(const void* p) {
    uint32_t a;
    asm("{ .reg .u64 t; cvta.to.shared.u64 t, %1; cvt.u32.u64 %0, t; }"
        : "=r"(a) : "l"(p));
    return a;
}
__device__ __forceinline__ void cp_async16(uint32_t dst, const void* src) {
    asm volatile("cp.async.cg.shared.global [%0], [%1], 16;"
                 :: "r"(dst), "l"(src) : "memory");
}
__device__ __forceinline__ void cp_commit() {
    asm volatile("cp.async.commit_group;" ::: "memory");
}
template <int N>
__device__ __forceinline__ void cp_wait() {
    asm volatile("cp.async.wait_group %0;" :: "n"(N) : "memory");
}
__device__ __forceinline__ float f2tf_f(float x) {
    uint32_t r;
    asm("cvt.rna.tf32.f32 %0, %1;" : "=r"(r) : "f"(x));
    return __uint_as_float(r);
}
__device__ __forceinline__ uint32_t f2tf_u(uint32_t x) {
    uint32_t r;
    asm("cvt.rna.tf32.f32 %0, %1;" : "=r"(r) : "r"(x));
    return r;
}
__device__ __forceinline__ void ldsm4(uint32_t* r, uint32_t addr) {
    asm volatile("ldmatrix.sync.aligned.m8n8.x4.shared.b16 {%0,%1,%2,%3}, [%4];"
                 : "=r"(r[0]), "=r"(r[1]), "=r"(r[2]), "=r"(r[3]) : "r"(addr));
}
__device__ __forceinline__ void mma_tf32(float* c, const uint32_t* a,
                                         const uint32_t* b) {
    asm volatile(
        "mma.sync.aligned.m16n8k8.row.col.f32.tf32.tf32.f32 "
        "{%0,%1,%2,%3}, {%4,%5,%6,%7}, {%8,%9}, {%0,%1,%2,%3};"
        : "+f"(c[0]), "+f"(c[1]), "+f"(c[2]), "+f"(c[3])
        : "r"(a[0]), "r"(a[1]), "r"(a[2]), "r"(a[3]), "r"(b[0]), "r"(b[1]));
}

// ===========================================================================
// Fused weight transpose + tf32 round: WT_z[n][k] = round(W_z[k][n]), z=0..3
// ===========================================================================
__global__ void __launch_bounds__(256) transpose_kernel(
    const float* __restrict__ w0, const float* __restrict__ w1,
    const float* __restrict__ w2, const float* __restrict__ w3,
    float* __restrict__ outbase)
{
    __shared__ float t[32][33];
    const int z = blockIdx.z;
    const float* in = (z == 0) ? w0 : (z == 1) ? w1 : (z == 2) ? w2 : w3;
    float* out = outbase + (size_t)z * D_MODEL * D_MODEL;
    const int bx = blockIdx.x * 32, by = blockIdx.y * 32;
#pragma unroll
    for (int i = threadIdx.y; i < 32; i += 8)
        t[i][threadIdx.x] = f2tf_f(in[(size_t)(by + i) * D_MODEL + bx + threadIdx.x]);
    __syncthreads();
#pragma unroll
    for (int i = threadIdx.y; i < 32; i += 8)
        out[(size_t)(bx + i) * D_MODEL + by + threadIdx.x] = t[threadIdx.x][i];
}

// ===========================================================================
// TF32 mma.sync GEMM core. CTA 128x128, BK=16, 8 warps, warp 64x32.
// 3-stage cp.async ring, ONE __syncthreads per k-iter.
// DO_CVT: round A-fragments in-loop (raw fp32 activations).
// DO_ROUND: round (and scale) outputs to tf32 at store (producer rounding).
// ===========================================================================
#define BK      16
#define SSTR    20
#define NKIT    (D_MODEL / BK)        // 64
#define BUFF    (128 * SSTR)          // floats per buffer (2560)
#define BUFB    (BUFF * 4)            // bytes per buffer (10240)
static constexpr int GEMM_SMEM = 6 * BUFB;   // 3 stages x (A+B) = 61440 B

template <int DO_CVT>
__device__ __forceinline__ void gemm_body(
    const float* __restrict__ X, const float* __restrict__ WT,
    const float* __restrict__ bias, const int* __restrict__ pos,
    float* __restrict__ out, bool do_rope, bool do_round, float oscale,
    float* __restrict__ As, float* __restrict__ Bs,
    int row0, int col0)
{
    const int tid  = threadIdx.x;
    const int wid  = tid >> 5, lane = tid & 31;
    const int g    = lane >> 2;
    const int t    = lane & 3;
    const int warpM = (wid >> 2) * 64;
    const int warpN = (wid & 3) * 32;

    const int arow = lane & 15, acolh = (lane >> 4) * 4;
    uint32_t aAddr[4];
#pragma unroll
    for (int i = 0; i < 4; i++)
        aAddr[i] = smem_u32(&As[(warpM + i * 16 + arow) * SSTR + acolh]);
    const int brow = lane & 7, bjh = lane >> 4, bcolh = ((lane >> 3) & 1) * 4;
    uint32_t bAddr[2];
#pragma unroll
    for (int p = 0; p < 2; p++)
        bAddr[p] = smem_u32(&Bs[(warpN + (2 * p + bjh) * 8 + brow) * SSTR + bcolh]);

    float c[4][4][4];
#pragma unroll
    for (int i = 0; i < 4; i++)
#pragma unroll
        for (int j = 0; j < 4; j++)
#pragma unroll
            for (int q = 0; q < 4; q++) c[i][j][q] = 0.f;

    auto stage = [&](int buf, int it) {
        const float* aSrc = X  + (size_t)row0 * D_MODEL + it * BK;
        const float* bSrc = WT + (size_t)col0 * D_MODEL + it * BK;
#pragma unroll
        for (int rep = 0; rep < 2; rep++) {
            int idx = rep * 256 + tid;          // 0..511
            int r = idx >> 2, c4 = (idx & 3) * 4;
            cp_async16(smem_u32(&As[buf * BUFF + r * SSTR + c4]),
                       aSrc + (size_t)r * D_MODEL + c4);
            cp_async16(smem_u32(&Bs[buf * BUFF + r * SSTR + c4]),
                       bSrc + (size_t)r * D_MODEL + c4);
        }
        cp_commit();
    };

    stage(0, 0);
    stage(1, 1);

#pragma unroll 1
    for (int it = 0; it < NKIT; it++) {
        if (it + 1 < NKIT) cp_wait<1>(); else cp_wait<0>();
        __syncthreads();
        if (it + 2 < NKIT) stage((it + 2) % 3, it + 2);

        const uint32_t bo = (uint32_t)(it % 3) * BUFB;
#pragma unroll
        for (int ks = 0; ks < 2; ks++) {
            const uint32_t ko = bo + ks * 32;   // 8 floats = 32 bytes
            uint32_t af[4][4], bf[2][4];
#pragma unroll
            for (int i = 0; i < 4; i++) ldsm4(af[i], aAddr[i] + ko);
#pragma unroll
            for (int p = 0; p < 2; p++) ldsm4(bf[p], bAddr[p] + ko);
            if (DO_CVT) {
#pragma unroll
                for (int i = 0; i < 4; i++)
#pragma unroll
                    for (int q = 0; q < 4; q++) af[i][q] = f2tf_u(af[i][q]);
            }
#pragma unroll
            for (int i = 0; i < 4; i++)
#pragma unroll
                for (int j = 0; j < 4; j++)
                    mma_tf32(c[i][j], af[i], &bf[j >> 1][(j & 1) * 2]);
        }
    }

    float invf[4];
    if (do_rope) {
#pragma unroll
        for (int j = 0; j < 4; j++) {
            int cg = col0 + warpN + j * 8 + 2 * t;
            int ii = (cg & (HEAD_DIM - 1)) >> 1;
            invf[j] = expf(-0.287823137f * (float)ii);   // ln(1e4)/32
        }
    }
#pragma unroll
    for (int i = 0; i < 4; i++) {
        const int r0 = row0 + warpM + i * 16 + g;
        const int r1 = r0 + 8;
        float p0 = 0.f, p1 = 0.f;
        if (do_rope) { p0 = (float)pos[r0]; p1 = (float)pos[r1]; }
#pragma unroll
        for (int j = 0; j < 4; j++) {
            const int cg = col0 + warpN + j * 8 + 2 * t;
            const float b0 = bias[cg], b1 = bias[cg + 1];
            float x0 = c[i][j][0] + b0, x1 = c[i][j][1] + b1;
            float y0 = c[i][j][2] + b0, y1 = c[i][j][3] + b1;
            if (do_rope) {
                float sn, cs;
                sincosf(p0 * invf[j], &sn, &cs);
                float t0 = x0 * cs - x1 * sn, t1 = x0 * sn + x1 * cs;
                x0 = t0; x1 = t1;
                sincosf(p1 * invf[j], &sn, &cs);
                t0 = y0 * cs - y1 * sn; t1 = y0 * sn + y1 * cs;
                y0 = t0; y1 = t1;
            }
            if (do_round) {
                x0 = f2tf_f(x0 * oscale); x1 = f2tf_f(x1 * oscale);
                y0 = f2tf_f(y0 * oscale); y1 = f2tf_f(y1 * oscale);
            }
            *(float2*)&out[(size_t)r0 * D_MODEL + cg] = make_float2(x0, x1);
            *(float2*)&out[(size_t)r1 * D_MODEL + cg] = make_float2(y0, y1);
        }
    }
}

// Fused Q/K/V projection: grid.z selects input/weight/bias/output.
// Outputs tf32-rounded; Q additionally scaled by 0.125 (exact).
__global__ void __launch_bounds__(256) gemm_qkv(
    const float* __restrict__ query, const float* __restrict__ key_,
    const float* __restrict__ value, const float* __restrict__ wtbase,
    const float* __restrict__ b_q, const float* __restrict__ b_k,
    const float* __restrict__ b_v, const int* __restrict__ pos,
    float* __restrict__ oQ, float* __restrict__ oK, float* __restrict__ oV)
{
    extern __shared__ float gsm[];
    const int z = blockIdx.z;
    const float* X    = (z == 0) ? query : (z == 1) ? key_ : value;
    const float* WT   = wtbase + (size_t)z * D_MODEL * D_MODEL;
    const float* bias = (z == 0) ? b_q : (z == 1) ? b_k : b_v;
    float* out        = (z == 0) ? oQ : (z == 1) ? oK : oV;
    gemm_body<1>(X, WT, bias, pos, out, z < 2, true,
                 (z == 0) ? 0.125f : 1.0f,
                 gsm, gsm + 3 * BUFF, blockIdx.y * 128, blockIdx.x * 128);
}

// Output projection: A (g_O) already tf32-rounded by attention; no out-round.
__global__ void __launch_bounds__(256) gemm_o(
    const float* __restrict__ X, const float* __restrict__ WT,
    const float* __restrict__ bias, float* __restrict__ out)
{
    extern __shared__ float gsm[];
    gemm_body<0>(X, WT, bias, nullptr, out, false, false, 1.0f,
                 gsm, gsm + 3 * BUFF, blockIdx.y * 128, blockIdx.x * 128);
}

// ===========================================================================
// Flash attention, causal — tf32 mma for S=QK^T and O=PV.
// 128 threads (4 warps); 64x64 tiles; Q/K/V pre-rounded+scaled by producer,
// loaded via cp.async with double-buffered K/V.
// ===========================================================================
#define ASTR 68
#define KVF  (64 * ASTR)                 // floats per tile buffer
#define KVB  (KVF * 4)                   // bytes per tile buffer
static constexpr int ATTN_SMEM_BYTES = 6 * KVB;   // Q + 2K + 2V + P = 104448

__global__ void __launch_bounds__(128) attn_kernel()
{
    extern __shared__ float smf[];
    float* Qs = smf;                 // [64][ASTR]
    float* Ks = Qs + KVF;            // 2 buffers
    float* Vs = Ks + 2 * KVF;        // 2 buffers
    float* Ps = Vs + 2 * KVF;        // per-warp 16-row regions

    const int tid   = threadIdx.x;
    const int w     = tid >> 5, lane = tid & 31;
    const int g     = lane >> 2, t = lane & 3;
    const int qtile = blockIdx.x;
    const int h     = blockIdx.y;
    const int b     = blockIdx.z;
    const int qrow0 = b * SEQ + qtile * 64;
    const int cb    = h * HEAD_DIM;

    auto stage_kv = [&](int buf, int kt) {
        const int krow0 = b * SEQ + kt * 64;
#pragma unroll
        for (int itr = 0; itr < 8; itr++) {
            int e = itr * 128 + tid;
            int r = e >> 4, c = (e & 15) * 4;
            cp_async16(smem_u32(&Ks[buf * KVF + r * ASTR + c]),
                       &g_K[(size_t)(krow0 + r) * D_MODEL + cb + c]);
            cp_async16(smem_u32(&Vs[buf * KVF + r * ASTR + c]),
                       &g_V[(size_t)(krow0 + r) * D_MODEL + cb + c]);
        }
    };

    // prologue: Q + first K/V tile as one group
#pragma unroll
    for (int itr = 0; itr < 8; itr++) {
        int e = itr * 128 + tid;
        int r = e >> 4, c = (e & 15) * 4;
        cp_async16(smem_u32(&Qs[r * ASTR + c]),
                   &g_Q[(size_t)(qrow0 + r) * D_MODEL + cb + c]);
    }
    stage_kv(0, 0);
    cp_commit();

    const uint32_t aQ = smem_u32(&Qs[(w * 16 + (lane & 15)) * ASTR + (lane >> 4) * 4]);
    const uint32_t aP = smem_u32(&Ps[(w * 16 + (lane & 15)) * ASTR + (lane >> 4) * 4]);
    uint32_t bK[4];
#pragma unroll
    for (int p = 0; p < 4; p++)
        bK[p] = smem_u32(&Ks[((2 * p + (lane >> 4)) * 8 + (lane & 7)) * ASTR +
                             ((lane >> 3) & 1) * 4]);

    float cO[8][4];
#pragma unroll
    for (int j = 0; j < 8; j++)
#pragma unroll
        for (int q = 0; q < 4; q++) cO[j][q] = 0.f;
    float m0 = -1e30f, m1 = -1e30f, l0 = 0.f, l1 = 0.f;

    const int q0 = w * 16 + g;
    const int q1 = q0 + 8;

#pragma unroll 1
    for (int kt = 0; kt <= qtile; kt++) {
        __syncthreads();   // all threads done reading buf (kt+1)&1 from iter kt-1
        if (kt + 1 <= qtile) {
            stage_kv((kt + 1) & 1, kt + 1);
            cp_commit();
            cp_wait<1>();
        } else {
            cp_wait<0>();
        }
        __syncthreads();   // data for tile kt visible to all

        const uint32_t kvbo = (uint32_t)(kt & 1) * KVB;

        // ---- S = Q @ K^T  (Q pre-scaled by 1/8) ----
        float cS[8][4];
#pragma unroll
        for (int j = 0; j < 8; j++)
#pragma unroll
            for (int q = 0; q < 4; q++) cS[j][q] = 0.f;
#pragma unroll
        for (int ks = 0; ks < 8; ks++) {
            uint32_t af[4], bf[4][4];
            ldsm4(af, aQ + ks * 32);
#pragma unroll
            for (int p = 0; p < 4; p++) ldsm4(bf[p], bK[p] + kvbo + ks * 32);
#pragma unroll
            for (int j = 0; j < 8; j++)
                mma_tf32(cS[j], af, &bf[j >> 1][(j & 1) * 2]);
        }

        if (kt == qtile) {
#pragma unroll
            for (int j = 0; j < 8; j++) {
                int kp = j * 8 + 2 * t;
                if (kp     > q0) cS[j][0] = -1e30f;
                if (kp + 1 > q0) cS[j][1] = -1e30f;
                if (kp     > q1) cS[j][2] = -1e30f;
                if (kp + 1 > q1) cS[j][3] = -1e30f;
            }
        }

        // ---- online softmax ----
        float mt0 = -1e30f, mt1 = -1e30f;
#pragma unroll
        for (int j = 0; j < 8; j++) {
            mt0 = fmaxf(mt0, fmaxf(cS[j][0], cS[j][1]));
            mt1 = fmaxf(mt1, fmaxf(cS[j][2], cS[j][3]));
        }
        mt0 = fmaxf(mt0, __shfl_xor_sync(0xffffffffu, mt0, 1));
        mt0 = fmaxf(mt0, __shfl_xor_sync(0xffffffffu, mt0, 2));
        mt1 = fmaxf(mt1, __shfl_xor_sync(0xffffffffu, mt1, 1));
        mt1 = fmaxf(mt1, __shfl_xor_sync(0xffffffffu, mt1, 2));
        const float mn0 = fmaxf(m0, mt0), mn1 = fmaxf(m1, mt1);
        const float f0 = __expf(m0 - mn0), f1 = __expf(m1 - mn1);
        float s0 = 0.f, s1 = 0.f;
#pragma unroll
        for (int j = 0; j < 8; j++) {
            cS[j][0] = __expf(cS[j][0] - mn0); s0 += cS[j][0];
            cS[j][1] = __expf(cS[j][1] - mn0); s0 += cS[j][1];
            cS[j][2] = __expf(cS[j][2] - mn1); s1 += cS[j][2];
            cS[j][3] = __expf(cS[j][3] - mn1); s1 += cS[j][3];
        }
        s0 += __shfl_xor_sync(0xffffffffu, s0, 1);
        s0 += __shfl_xor_sync(0xffffffffu, s0, 2);
        s1 += __shfl_xor_sync(0xffffffffu, s1, 1);
        s1 += __shfl_xor_sync(0xffffffffu, s1, 2);
        l0 = l0 * f0 + s0;  l1 = l1 * f1 + s1;
        m0 = mn0;           m1 = mn1;
#pragma unroll
        for (int j = 0; j < 8; j++) {
            cO[j][0] *= f0; cO[j][1] *= f0;
            cO[j][2] *= f1; cO[j][3] *= f1;
        }

        // ---- P to per-warp smem (tf32-rounded) ----
#pragma unroll
        for (int j = 0; j < 8; j++) {
            *(float2*)&Ps[q0 * ASTR + j * 8 + 2 * t] =
                make_float2(f2tf_f(cS[j][0]), f2tf_f(cS[j][1]));
            *(float2*)&Ps[q1 * ASTR + j * 8 + 2 * t] =
                make_float2(f2tf_f(cS[j][2]), f2tf_f(cS[j][3]));
        }
        __syncwarp();

        // ---- O += P @ V ----
#pragma unroll
        for (int ks = 0; ks < 8; ks++) {
            uint32_t ap[4];
            ldsm4(ap, aP + ks * 32);
            const float* vb = &Vs[(kt & 1) * KVF + (ks * 8 + t) * ASTR + g];
#pragma unroll
            for (int j = 0; j < 8; j++) {
                uint32_t bv[2];
                bv[0] = __float_as_uint(vb[j * 8]);
                bv[1] = __float_as_uint(vb[4 * ASTR + j * 8]);
                mma_tf32(cO[j], ap, bv);
            }
        }
    }

    // ---- epilogue: normalize, round (feeds gemm_o), store ----
    const float inv0 = 1.f / l0, inv1 = 1.f / l1;
    float* dst0 = &g_O[(size_t)(qrow0 + q0) * D_MODEL + cb];
    float* dst1 = &g_O[(size_t)(qrow0 + q1) * D_MODEL + cb];
#pragma unroll
    for (int j = 0; j < 8; j++) {
        *(float2*)&dst0[j * 8 + 2 * t] =
            make_float2(f2tf_f(cO[j][0] * inv0), f2tf_f(cO[j][1] * inv0));
        *(float2*)&dst1[j * 8 + 2 * t] =
            make_float2(f2tf_f(cO[j][2] * inv1), f2tf_f(cO[j][3] * inv1));
    }
}

// ---------------------------------------------------------------------------
extern "C" void kernel_launch(void* const* d_in, const int* in_sizes, int n_in,
                              void* d_out, int out_size)
{
    (void)in_sizes; (void)n_in; (void)out_size;
    const float* query = (const float*)d_in[0];
    const float* key_  = (const float*)d_in[1];
    const float* value = (const float*)d_in[2];
    const int*   pos   = (const int*)d_in[3];
    const float* w_q   = (const float*)d_in[4];
    const float* b_q   = (const float*)d_in[5];
    const float* w_k   = (const float*)d_in[6];
    const float* b_k   = (const float*)d_in[7];
    const float* w_v   = (const float*)d_in[8];
    const float* b_v   = (const float*)d_in[9];
    const float* w_o   = (const float*)d_in[10];
    const float* b_o   = (const float*)d_in[11];
    float* out = (float*)d_out;

    float *pQ, *pK, *pV, *pO, *pWT;
    cudaGetSymbolAddress((void**)&pQ, g_Q);
    cudaGetSymbolAddress((void**)&pK, g_K);
    cudaGetSymbolAddress((void**)&pV, g_V);
    cudaGetSymbolAddress((void**)&pO, g_O);
    cudaGetSymbolAddress((void**)&pWT, g_WT);
    float* wto = pWT + 3 * (size_t)D_MODEL * D_MODEL;

    cudaFuncSetAttribute(attn_kernel,
                         cudaFuncAttributeMaxDynamicSharedMemorySize,
                         ATTN_SMEM_BYTES);
    cudaFuncSetAttribute(gemm_qkv,
                         cudaFuncAttributeMaxDynamicSharedMemorySize, GEMM_SMEM);
    cudaFuncSetAttribute(gemm_o,
                         cudaFuncAttributeMaxDynamicSharedMemorySize, GEMM_SMEM);

    transpose_kernel<<<dim3(32, 32, 4), dim3(32, 8)>>>(w_q, w_k, w_v, w_o, pWT);

    gemm_qkv<<<dim3(D_MODEL / 128, ROWS / 128, 3), 256, GEMM_SMEM>>>(
        query, key_, value, pWT, b_q, b_k, b_v, pos, pQ, pK, pV);

    attn_kernel<<<dim3(SEQ / 64, NUM_HEADS, BATCH), 128, ATTN_SMEM_BYTES>>>();

    gemm_o<<<dim3(D_MODEL / 128, ROWS / 128), 256, GEMM_SMEM>>>(pO, wto, b_o, out);
}